// round 13
// baseline (speedup 1.0000x reference)
#include <cuda_runtime.h>
#include <cuda_fp16.h>
#include <math.h>
#include <stdint.h>

#define NN 100000
#define NPAD 100128
#define DD 128
#define DD2 256
#define EE 800000
#define NB ((NN + 255) / 256)
#define STRD 48          // k16 chunk: 16 elems*2B = 32B + 16B pad -> LDSM conflict-free
#define SEG 6144         // 128*48
#define CHSZ3 18432      // 3 segments (A, B_hi, B_lo)
#define CHSZ4 24576      // 4 segments (A_hi, A_lo, B_hi, B_lo)

// ================= scratch =================
__device__ float g_hA[NN * DD];
__device__ float g_hB[NN * DD];
__device__ float g_statS[4 * DD2];
__device__ float g_statQ[4 * DD2];
__device__ __align__(256) __half g_h1h[NPAD * DD2];   // h1 hi (layers 0/1)
__device__ __align__(256) __half g_h1l[NPAD * DD2];   // h1 lo
__device__ __align__(256) __half g_h1f[NPAD * DD2];   // h1 single fp16 (final z=0)
__device__ __align__(256) __half g_h1fb[NPAD * DD2];  // (final z=1)
__device__ __align__(256) __half g_ahh[NPAD * DD];    // aggr out hi (layers 0,1)
__device__ __align__(256) __half g_ahl[NPAD * DD];    // aggr out lo
__device__ __align__(256) __half g_af16[NPAD * DD];   // aggr out fp16 (layer 2)
__device__ __align__(256) __half g_af16b[NPAD * DD];  // (layer 3)
__device__ __align__(256) __half g_w1h[4 * 256 * 128];
__device__ __align__(256) __half g_w1l[4 * 256 * 128];
__device__ __align__(256) __half g_w2h[4 * 128 * 256];
__device__ __align__(256) __half g_w2l[4 * 128 * 256];
__device__ int g_deg[NN];
__device__ int g_scan[NN];
__device__ int g_bsum[512];
__device__ int g_boff[512];
__device__ int g_rowptr[NN + 1];
__device__ int g_cursor[NN];
__device__ int g_csr_src[EE];

// ================= small helpers =================
__device__ __forceinline__ uint32_t smem_u32(const void* p) {
    uint32_t a;
    asm("{ .reg .u64 t; cvta.to.shared.u64 t, %1; cvt.u32.u64 %0, t; }"
        : "=r"(a) : "l"(p));
    return a;
}
#define CP_ASYNC16(sa, ga) \
    asm volatile("cp.async.cg.shared.global [%0], [%1], 16;" :: "r"(sa), "l"(ga))
#define CP_COMMIT() asm volatile("cp.async.commit_group;")
#define CP_WAIT0() asm volatile("cp.async.wait_group 0;")
#define CP_WAIT1() asm volatile("cp.async.wait_group 1;")
#define CP_WAIT2() asm volatile("cp.async.wait_group 2;")

__device__ __forceinline__ void ldsm_x4(uint32_t* r, uint32_t addr) {
    asm volatile("ldmatrix.sync.aligned.m8n8.x4.shared.b16 {%0,%1,%2,%3}, [%4];"
                 : "=r"(r[0]), "=r"(r[1]), "=r"(r[2]), "=r"(r[3]) : "r"(addr));
}
__device__ __forceinline__ void mma_f16(float* c, const uint32_t* a, const uint32_t* b) {
    asm volatile(
        "mma.sync.aligned.m16n8k16.row.col.f32.f16.f16.f32 "
        "{%0,%1,%2,%3}, {%4,%5,%6,%7}, {%8,%9}, {%0,%1,%2,%3};"
        : "+f"(c[0]), "+f"(c[1]), "+f"(c[2]), "+f"(c[3])
        : "r"(a[0]), "r"(a[1]), "r"(a[2]), "r"(a[3]), "r"(b[0]), "r"(b[1]));
}

// BN+ReLU on A fragment pair (hi/lo), in place. Fragment k map: regs{0,1}->k,
// regs{2,3}->k+8 with k = kbase + (lane&3)*2.
__device__ __forceinline__ void bn_frag3(uint32_t ah[4], uint32_t al[4],
                                         const float* sc, const float* sh,
                                         int kbase, int lane) {
    int k0 = kbase + (lane & 3) * 2;
#pragma unroll
    for (int h8 = 0; h8 < 2; h8++) {
        float2 scv = *(const float2*)&sc[k0 + h8 * 8];
        float2 shv = *(const float2*)&sh[k0 + h8 * 8];
#pragma unroll
        for (int ri = 0; ri < 2; ri++) {
            int idx = h8 * 2 + ri;
            float2 v = __half22float2(*(__half2*)&ah[idx]);
            float2 w = __half22float2(*(__half2*)&al[idx]);
            v.x = fmaxf((v.x + w.x) * scv.x + shv.x, 0.f);
            v.y = fmaxf((v.y + w.y) * scv.y + shv.y, 0.f);
            __half2 nh = __float22half2_rn(v);
            __half2 nl = __floats2half2_rn(v.x - __low2float(nh),
                                           v.y - __high2float(nh));
            ah[idx] = *(uint32_t*)&nh;
            al[idx] = *(uint32_t*)&nl;
        }
    }
}
__device__ __forceinline__ void bn_frag2(uint32_t a[4], const float* sc, const float* sh,
                                         int kbase, int lane) {
    int k0 = kbase + (lane & 3) * 2;
#pragma unroll
    for (int h8 = 0; h8 < 2; h8++) {
        float2 scv = *(const float2*)&sc[k0 + h8 * 8];
        float2 shv = *(const float2*)&sh[k0 + h8 * 8];
#pragma unroll
        for (int ri = 0; ri < 2; ri++) {
            int idx = h8 * 2 + ri;
            float2 v = __half22float2(*(__half2*)&a[idx]);
            v.x = fmaxf(v.x * scv.x + shv.x, 0.f);
            v.y = fmaxf(v.y * scv.y + shv.y, 0.f);
            __half2 nh = __float22half2_rn(v);
            a[idx] = *(uint32_t*)&nh;
        }
    }
}

// ---- 2-pass chunk: segs [A, Bh, Bl]; optional fragment BN ----
template <bool BN>
__device__ __forceinline__ void mma_chunk2(uint32_t buf, int wm, int wn, int g, int r,
                                           float c[2][8][4],
                                           const float* sc, const float* sh,
                                           int kbase, int lane) {
    uint32_t a[2][4], bf[16];
    uint32_t acol = (uint32_t)(g >> 1) * 16;
    uint32_t bcol = (uint32_t)(g & 1) * 16;
#pragma unroll
    for (int mt = 0; mt < 2; mt++) {
        uint32_t arow = (uint32_t)(wm + mt * 16 + (g & 1) * 8 + r);
        ldsm_x4(a[mt], buf + arow * STRD + acol);
        if (BN) bn_frag2(a[mt], sc, sh, kbase, lane);
    }
#pragma unroll
    for (int nb = 0; nb < 4; nb++) {
        uint32_t brow = (uint32_t)(wn + nb * 16 + (g >> 1) * 8 + r);
        ldsm_x4(&bf[nb * 4], buf + SEG + brow * STRD + bcol);
    }
#pragma unroll
    for (int mt = 0; mt < 2; mt++)
#pragma unroll
        for (int nt = 0; nt < 8; nt++) mma_f16(c[mt][nt], a[mt], &bf[nt * 2]);
#pragma unroll
    for (int nb = 0; nb < 4; nb++) {
        uint32_t brow = (uint32_t)(wn + nb * 16 + (g >> 1) * 8 + r);
        ldsm_x4(&bf[nb * 4], buf + 2 * SEG + brow * STRD + bcol);
    }
#pragma unroll
    for (int mt = 0; mt < 2; mt++)
#pragma unroll
        for (int nt = 0; nt < 8; nt++) mma_f16(c[mt][nt], a[mt], &bf[nt * 2]);
}

// ---- 3-pass chunk: segs [Ah, Al, Bh, Bl]; C += Ah*Bh + Al*Bh + Ah*Bl ----
template <bool BN>
__device__ __forceinline__ void mma_chunk3(uint32_t buf, int wm, int wn, int g, int r,
                                           float c[2][8][4],
                                           const float* sc, const float* sh,
                                           int kbase, int lane) {
    uint32_t ah[2][4], al[2][4], bf[16];
    uint32_t acol = (uint32_t)(g >> 1) * 16;
    uint32_t bcol = (uint32_t)(g & 1) * 16;
#pragma unroll
    for (int mt = 0; mt < 2; mt++) {
        uint32_t arow = (uint32_t)(wm + mt * 16 + (g & 1) * 8 + r);
        ldsm_x4(ah[mt], buf + arow * STRD + acol);
        ldsm_x4(al[mt], buf + SEG + arow * STRD + acol);
        if (BN) bn_frag3(ah[mt], al[mt], sc, sh, kbase, lane);
    }
#pragma unroll
    for (int nb = 0; nb < 4; nb++) {
        uint32_t brow = (uint32_t)(wn + nb * 16 + (g >> 1) * 8 + r);
        ldsm_x4(&bf[nb * 4], buf + 2 * SEG + brow * STRD + bcol);
    }
#pragma unroll
    for (int mt = 0; mt < 2; mt++)
#pragma unroll
        for (int nt = 0; nt < 8; nt++) mma_f16(c[mt][nt], ah[mt], &bf[nt * 2]);
#pragma unroll
    for (int mt = 0; mt < 2; mt++)
#pragma unroll
        for (int nt = 0; nt < 8; nt++) mma_f16(c[mt][nt], al[mt], &bf[nt * 2]);
#pragma unroll
    for (int nb = 0; nb < 4; nb++) {
        uint32_t brow = (uint32_t)(wn + nb * 16 + (g >> 1) * 8 + r);
        ldsm_x4(&bf[nb * 4], buf + 3 * SEG + brow * STRD + bcol);
    }
#pragma unroll
    for (int mt = 0; mt < 2; mt++)
#pragma unroll
        for (int nt = 0; nt < 8; nt++) mma_f16(c[mt][nt], ah[mt], &bf[nt * 2]);
}

// cp.async one segment: 128 rows x 32B/row
template <typename T>
__device__ __forceinline__ void seg_cp(uint32_t sm, const T* gsrc,
                                       int row0g, int ldk, int k0, int tid) {
    int m = tid >> 1, sub = tid & 1;
    uint32_t sa = sm + m * STRD + sub * 16;
    const void* ga = gsrc + (size_t)(row0g + m) * ldk + k0 + sub * 8;
    CP_ASYNC16(sa, ga);
}

// ---- epilogue pieces ----
__device__ __forceinline__ void store_f32(float c[2][8][4], float* C, int row0, int col0,
                                          int NOUT, int wm, int wn, int lane, int M,
                                          bool relu) {
#pragma unroll
    for (int mt = 0; mt < 2; mt++) {
        int rb = row0 + wm + mt * 16 + (lane >> 2);
#pragma unroll
        for (int nt = 0; nt < 8; nt++) {
            int cb = col0 + wn + nt * 8 + (lane & 3) * 2;
            float2 v0 = make_float2(c[mt][nt][0], c[mt][nt][1]);
            float2 v1 = make_float2(c[mt][nt][2], c[mt][nt][3]);
            if (relu) {
                v0.x = fmaxf(v0.x, 0.f); v0.y = fmaxf(v0.y, 0.f);
                v1.x = fmaxf(v1.x, 0.f); v1.y = fmaxf(v1.y, 0.f);
            }
            if (rb < M)     *(float2*)&C[(size_t)rb * NOUT + cb] = v0;
            if (rb + 8 < M) *(float2*)&C[(size_t)(rb + 8) * NOUT + cb] = v1;
        }
    }
}
__device__ __forceinline__ void store_hl(float c[2][8][4], __half* Hh, __half* Hl,
                                         int row0, int col0, int wm, int wn,
                                         int lane, int M) {
#pragma unroll
    for (int mt = 0; mt < 2; mt++) {
        int rb = row0 + wm + mt * 16 + (lane >> 2);
#pragma unroll
        for (int nt = 0; nt < 8; nt++) {
            int cb = col0 + wn + nt * 8 + (lane & 3) * 2;
            __half2 h0 = __floats2half2_rn(c[mt][nt][0], c[mt][nt][1]);
            __half2 l0 = __floats2half2_rn(c[mt][nt][0] - __low2float(h0),
                                           c[mt][nt][1] - __high2float(h0));
            __half2 h1 = __floats2half2_rn(c[mt][nt][2], c[mt][nt][3]);
            __half2 l1 = __floats2half2_rn(c[mt][nt][2] - __low2float(h1),
                                           c[mt][nt][3] - __high2float(h1));
            if (rb < M) {
                *(uint32_t*)&Hh[(size_t)rb * DD2 + cb] = *(uint32_t*)&h0;
                *(uint32_t*)&Hl[(size_t)rb * DD2 + cb] = *(uint32_t*)&l0;
            }
            if (rb + 8 < M) {
                *(uint32_t*)&Hh[(size_t)(rb + 8) * DD2 + cb] = *(uint32_t*)&h1;
                *(uint32_t*)&Hl[(size_t)(rb + 8) * DD2 + cb] = *(uint32_t*)&l1;
            }
        }
    }
}
__device__ __forceinline__ void store_h(float c[2][8][4], __half* H,
                                        int row0, int col0, int wm, int wn,
                                        int lane, int M) {
#pragma unroll
    for (int mt = 0; mt < 2; mt++) {
        int rb = row0 + wm + mt * 16 + (lane >> 2);
#pragma unroll
        for (int nt = 0; nt < 8; nt++) {
            int cb = col0 + wn + nt * 8 + (lane & 3) * 2;
            __half2 h0 = __floats2half2_rn(c[mt][nt][0], c[mt][nt][1]);
            __half2 h1 = __floats2half2_rn(c[mt][nt][2], c[mt][nt][3]);
            if (rb < M)     *(uint32_t*)&H[(size_t)rb * DD2 + cb] = *(uint32_t*)&h0;
            if (rb + 8 < M) *(uint32_t*)&H[(size_t)(rb + 8) * DD2 + cb] = *(uint32_t*)&h1;
        }
    }
}
__device__ __forceinline__ void bn_stats_epi(float c[2][8][4], float* statS, float* statQ,
                                             int col0, int wn, int lane) {
    float s16[16], q16[16];
#pragma unroll
    for (int nt = 0; nt < 8; nt++)
#pragma unroll
        for (int j = 0; j < 2; j++) {
            float a0 = c[0][nt][j], a1 = c[0][nt][j + 2];
            float a2 = c[1][nt][j], a3 = c[1][nt][j + 2];
            s16[nt * 2 + j] = a0 + a1 + a2 + a3;
            q16[nt * 2 + j] = a0 * a0 + a1 * a1 + a2 * a2 + a3 * a3;
        }
#pragma unroll
    for (int i = 0; i < 16; i++) {
#pragma unroll
        for (int off = 4; off < 32; off <<= 1) {
            s16[i] += __shfl_xor_sync(0xffffffffu, s16[i], off);
            q16[i] += __shfl_xor_sync(0xffffffffu, q16[i], off);
        }
    }
    if ((lane >> 2) == 0) {
#pragma unroll
        for (int nt = 0; nt < 8; nt++)
#pragma unroll
            for (int j = 0; j < 2; j++) {
                int col = col0 + wn + nt * 8 + (lane & 3) * 2 + j;
                atomicAdd(&statS[col], s16[nt * 2 + j]);
                atomicAdd(&statQ[col], q16[nt * 2 + j]);
            }
    }
}

// ===== GEMM1 3-pass (layers 0,1): epilogue -> h1 fp16 hi/lo + stats =====
__global__ void __launch_bounds__(256, 2)
gemm1_p3(const __half* __restrict__ Ah, const __half* __restrict__ Al,
         const __half* __restrict__ Bh, const __half* __restrict__ Bl,
         __half* __restrict__ Ch, __half* __restrict__ Cl,
         float* __restrict__ statS, float* __restrict__ statQ, int M) {
    extern __shared__ __align__(128) char dsm[];
    const uint32_t base = smem_u32(dsm);
    constexpr int KTOT = 128, NC = 8;

    int tid = threadIdx.x;
    int wid = tid >> 5, lane = tid & 31;
    int wm = (wid & 3) * 32, wn = (wid >> 2) * 64;
    int row0 = blockIdx.y * 128, col0 = blockIdx.x * 128;
    int g = lane >> 3, r = lane & 7;

    float c[2][8][4];
#pragma unroll
    for (int i = 0; i < 2; i++)
#pragma unroll
        for (int j = 0; j < 8; j++)
#pragma unroll
            for (int q = 0; q < 4; q++) c[i][j][q] = 0.0f;

    auto stage = [&](int ch) {
        uint32_t b = base + (ch & 3) * CHSZ4;
        int k0 = ch * 16;
        seg_cp(b + 0 * SEG, Ah, row0, KTOT, k0, tid);
        seg_cp(b + 1 * SEG, Al, row0, KTOT, k0, tid);
        seg_cp(b + 2 * SEG, Bh, col0, KTOT, k0, tid);
        seg_cp(b + 3 * SEG, Bl, col0, KTOT, k0, tid);
        CP_COMMIT();
    };

    stage(0); stage(1); stage(2);

#pragma unroll 1
    for (int ch = 0; ch < NC - 3; ch++) {
        CP_WAIT2();
        __syncthreads();
        stage(ch + 3);
        mma_chunk3<false>(base + (ch & 3) * CHSZ4, wm, wn, g, r, c, nullptr, nullptr, 0, lane);
    }
    CP_WAIT2(); __syncthreads();
    mma_chunk3<false>(base + ((NC - 3) & 3) * CHSZ4, wm, wn, g, r, c, nullptr, nullptr, 0, lane);
    CP_WAIT1(); __syncthreads();
    mma_chunk3<false>(base + ((NC - 2) & 3) * CHSZ4, wm, wn, g, r, c, nullptr, nullptr, 0, lane);
    CP_WAIT0(); __syncthreads();
    mma_chunk3<false>(base + ((NC - 1) & 3) * CHSZ4, wm, wn, g, r, c, nullptr, nullptr, 0, lane);

    store_hl(c, Ch, Cl, row0, col0, wm, wn, lane, M);
    bn_stats_epi(c, statS, statQ, col0, wn, lane);
}

// ===== GEMM1 2-pass (layers 2,3 z-batched): epilogue -> h1 single fp16 + stats ===
__global__ void __launch_bounds__(256, 2)
gemm1_p2(const __half* __restrict__ A0, const __half* __restrict__ A1,
         const __half* __restrict__ Bh_base, const __half* __restrict__ Bl_base,
         __half* __restrict__ C0, __half* __restrict__ C1,
         float* __restrict__ statS_base, float* __restrict__ statQ_base, int M) {
    extern __shared__ __align__(128) char dsm[];
    const uint32_t base = smem_u32(dsm);
    constexpr int KTOT = 128, NOUT = 256, NC = 8;

    int z = blockIdx.z;
    const __half* Af = z ? A1 : A0;
    const __half* Bh = Bh_base + (size_t)z * KTOT * NOUT;
    const __half* Bl = Bl_base + (size_t)z * KTOT * NOUT;
    __half* C = z ? C1 : C0;

    int tid = threadIdx.x;
    int wid = tid >> 5, lane = tid & 31;
    int wm = (wid & 3) * 32, wn = (wid >> 2) * 64;
    int row0 = blockIdx.y * 128, col0 = blockIdx.x * 128;
    int g = lane >> 3, r = lane & 7;

    float c[2][8][4];
#pragma unroll
    for (int i = 0; i < 2; i++)
#pragma unroll
        for (int j = 0; j < 8; j++)
#pragma unroll
            for (int q = 0; q < 4; q++) c[i][j][q] = 0.0f;

    auto stage = [&](int ch) {
        uint32_t b = base + (ch & 3) * CHSZ3;
        int k0 = ch * 16;
        seg_cp(b + 0 * SEG, Af, row0, KTOT, k0, tid);
        seg_cp(b + 1 * SEG, Bh, col0, KTOT, k0, tid);
        seg_cp(b + 2 * SEG, Bl, col0, KTOT, k0, tid);
        CP_COMMIT();
    };

    stage(0); stage(1); stage(2);

#pragma unroll 1
    for (int ch = 0; ch < NC - 3; ch++) {
        CP_WAIT2();
        __syncthreads();
        stage(ch + 3);
        mma_chunk2<false>(base + (ch & 3) * CHSZ3, wm, wn, g, r, c, nullptr, nullptr, 0, lane);
    }
    CP_WAIT2(); __syncthreads();
    mma_chunk2<false>(base + ((NC - 3) & 3) * CHSZ3, wm, wn, g, r, c, nullptr, nullptr, 0, lane);
    CP_WAIT1(); __syncthreads();
    mma_chunk2<false>(base + ((NC - 2) & 3) * CHSZ3, wm, wn, g, r, c, nullptr, nullptr, 0, lane);
    CP_WAIT0(); __syncthreads();
    mma_chunk2<false>(base + ((NC - 1) & 3) * CHSZ3, wm, wn, g, r, c, nullptr, nullptr, 0, lane);

    store_h(c, C, row0, col0, wm, wn, lane, M);
    bn_stats_epi(c, statS_base + z * DD2, statQ_base + z * DD2, col0, wn, lane);
}

// ===== GEMM2 3-pass (layers 0,1): fp16 hi/lo A via cp.async + fragment BN =====
__global__ void __launch_bounds__(256, 2)
gemm2_p3(const __half* __restrict__ Ah, const __half* __restrict__ Al,
         const __half* __restrict__ Bh, const __half* __restrict__ Bl,
         float* __restrict__ C,
         const float* __restrict__ gamma, const float* __restrict__ beta,
         int l, int M) {
    extern __shared__ __align__(128) char dsm[];
    __shared__ float s_sc[DD2];
    __shared__ float s_sh[DD2];
    const uint32_t base = smem_u32(dsm);
    constexpr int KTOT = 256, NOUT = 128, NC = 16;

    int tid = threadIdx.x;
    int wid = tid >> 5, lane = tid & 31;
    int wm = (wid & 3) * 32, wn = (wid >> 2) * 64;
    int row0 = blockIdx.y * 128;
    int g = lane >> 3, r = lane & 7;

    {
        int cc = tid;
        float s = g_statS[l * DD2 + cc];
        float q = g_statQ[l * DD2 + cc];
        float mean = s / (float)M;
        float var = q / (float)M - mean * mean;
        float inv = rsqrtf(var + 1e-5f);
        float sc = inv * gamma[l * DD2 + cc];
        s_sc[cc] = sc;
        s_sh[cc] = beta[l * DD2 + cc] - mean * sc;
    }

    float c[2][8][4];
#pragma unroll
    for (int i = 0; i < 2; i++)
#pragma unroll
        for (int j = 0; j < 8; j++)
#pragma unroll
            for (int q = 0; q < 4; q++) c[i][j][q] = 0.0f;

    auto stage = [&](int ch) {
        uint32_t b = base + (ch & 3) * CHSZ4;
        int k0 = ch * 16;
        seg_cp(b + 0 * SEG, Ah, row0, KTOT, k0, tid);
        seg_cp(b + 1 * SEG, Al, row0, KTOT, k0, tid);
        seg_cp(b + 2 * SEG, Bh, 0, KTOT, k0, tid);
        seg_cp(b + 3 * SEG, Bl, 0, KTOT, k0, tid);
        CP_COMMIT();
    };

    stage(0); stage(1); stage(2);

#pragma unroll 1
    for (int ch = 0; ch < NC - 3; ch++) {
        CP_WAIT2();
        __syncthreads();
        stage(ch + 3);
        mma_chunk3<true>(base + (ch & 3) * CHSZ4, wm, wn, g, r, c, s_sc, s_sh, ch * 16, lane);
    }
    CP_WAIT2(); __syncthreads();
    mma_chunk3<true>(base + ((NC - 3) & 3) * CHSZ4, wm, wn, g, r, c, s_sc, s_sh, (NC - 3) * 16, lane);
    CP_WAIT1(); __syncthreads();
    mma_chunk3<true>(base + ((NC - 2) & 3) * CHSZ4, wm, wn, g, r, c, s_sc, s_sh, (NC - 2) * 16, lane);
    CP_WAIT0(); __syncthreads();
    mma_chunk3<true>(base + ((NC - 1) & 3) * CHSZ4, wm, wn, g, r, c, s_sc, s_sh, (NC - 1) * 16, lane);

    store_f32(c, C, row0, 0, NOUT, wm, wn, lane, M, true);
}

// ===== GEMM2 2-pass (final mu/logstd, z-batched): fp16 A + fragment BN =====
__global__ void __launch_bounds__(256, 2)
gemm2_p2(const __half* __restrict__ A0, const __half* __restrict__ A1,
         const __half* __restrict__ Bh_base, const __half* __restrict__ Bl_base,
         float* __restrict__ C0, float* __restrict__ C1,
         const float* __restrict__ gamma, const float* __restrict__ beta,
         int layer0, int M) {
    extern __shared__ __align__(128) char dsm[];
    __shared__ float s_sc[DD2];
    __shared__ float s_sh[DD2];
    const uint32_t base = smem_u32(dsm);
    constexpr int KTOT = 256, NOUT = 128, NC = 16;

    int z = blockIdx.z;
    int l = layer0 + z;
    const __half* Af = z ? A1 : A0;
    const __half* Bh = Bh_base + (size_t)z * KTOT * NOUT;
    const __half* Bl = Bl_base + (size_t)z * KTOT * NOUT;
    float* C = z ? C1 : C0;

    int tid = threadIdx.x;
    int wid = tid >> 5, lane = tid & 31;
    int wm = (wid & 3) * 32, wn = (wid >> 2) * 64;
    int row0 = blockIdx.y * 128;
    int g = lane >> 3, r = lane & 7;

    {
        int cc = tid;
        float s = g_statS[l * DD2 + cc];
        float q = g_statQ[l * DD2 + cc];
        float mean = s / (float)M;
        float var = q / (float)M - mean * mean;
        float inv = rsqrtf(var + 1e-5f);
        float sc = inv * gamma[l * DD2 + cc];
        s_sc[cc] = sc;
        s_sh[cc] = beta[l * DD2 + cc] - mean * sc;
    }

    float c[2][8][4];
#pragma unroll
    for (int i = 0; i < 2; i++)
#pragma unroll
        for (int j = 0; j < 8; j++)
#pragma unroll
            for (int q = 0; q < 4; q++) c[i][j][q] = 0.0f;

    auto stage = [&](int ch) {
        uint32_t b = base + (ch & 3) * CHSZ3;
        int k0 = ch * 16;
        seg_cp(b + 0 * SEG, Af, row0, KTOT, k0, tid);
        seg_cp(b + 1 * SEG, Bh, 0, KTOT, k0, tid);
        seg_cp(b + 2 * SEG, Bl, 0, KTOT, k0, tid);
        CP_COMMIT();
    };

    stage(0); stage(1); stage(2);

#pragma unroll 1
    for (int ch = 0; ch < NC - 3; ch++) {
        CP_WAIT2();
        __syncthreads();
        stage(ch + 3);
        mma_chunk2<true>(base + (ch & 3) * CHSZ3, wm, wn, g, r, c, s_sc, s_sh, ch * 16, lane);
    }
    CP_WAIT2(); __syncthreads();
    mma_chunk2<true>(base + ((NC - 3) & 3) * CHSZ3, wm, wn, g, r, c, s_sc, s_sh, (NC - 3) * 16, lane);
    CP_WAIT1(); __syncthreads();
    mma_chunk2<true>(base + ((NC - 2) & 3) * CHSZ3, wm, wn, g, r, c, s_sc, s_sh, (NC - 2) * 16, lane);
    CP_WAIT0(); __syncthreads();
    mma_chunk2<true>(base + ((NC - 1) & 3) * CHSZ3, wm, wn, g, r, c, s_sc, s_sh, (NC - 1) * 16, lane);

    store_f32(c, C, row0, 0, NOUT, wm, wn, lane, M, false);
}

// ===== weight pack (fp16 hi/lo) + zero stats/deg =====
__global__ void pack_w_kernel(const float* __restrict__ W1, const float* __restrict__ W2,
                              int N) {
    int idx = blockIdx.x * blockDim.x + threadIdx.x;
    if (idx < 131072) {
        int l = idx >> 15, rr = idx & 32767;
        int k = rr >> 8, n = rr & 255;
        float v = W1[(size_t)l * 32768 + rr];
        __half h = __float2half_rn(v);
        __half lo = __float2half_rn(v - __half2float(h));
        int o = l * 32768 + n * 128 + k;
        g_w1h[o] = h; g_w1l[o] = lo;
    } else if (idx < 262144) {
        int j = idx - 131072;
        int l = j >> 15, rr = j & 32767;
        int k = rr >> 7, n = rr & 127;
        float v = W2[(size_t)l * 32768 + rr];
        __half h = __float2half_rn(v);
        __half lo = __float2half_rn(v - __half2float(h));
        int o = l * 32768 + n * 256 + k;
        g_w2h[o] = h; g_w2l[o] = lo;
    }
    if (idx < 1024) { g_statS[idx] = 0.f; g_statQ[idx] = 0.f; }
    if (idx < N) g_deg[idx] = 0;
}

// ================= CSR build =================
__global__ void hist_kernel(const int* __restrict__ dst, int E, int N) {
    int e = blockIdx.x * blockDim.x + threadIdx.x;
    if (e >= E) return;
    int d = dst[e];
    if ((unsigned)d < (unsigned)N) atomicAdd(&g_deg[d], 1);
}
__global__ void blockscan_kernel(int N) {
    __shared__ int sm[256];
    int i = blockIdx.x * 256 + threadIdx.x;
    int v = (i < N) ? g_deg[i] : 0;
    sm[threadIdx.x] = v;
    __syncthreads();
#pragma unroll
    for (int off = 1; off < 256; off <<= 1) {
        int t = (threadIdx.x >= off) ? sm[threadIdx.x - off] : 0;
        __syncthreads();
        sm[threadIdx.x] += t;
        __syncthreads();
    }
    if (i < N) g_scan[i] = sm[threadIdx.x];
    if (threadIdx.x == 255) g_bsum[blockIdx.x] = sm[255];
}
__global__ void scanbsum_kernel(int nb) {
    __shared__ int sm[512];
    int tid = threadIdx.x;
    int v = (tid < nb) ? g_bsum[tid] : 0;
    sm[tid] = v;
    __syncthreads();
#pragma unroll
    for (int off = 1; off < 512; off <<= 1) {
        int t = (tid >= off) ? sm[tid - off] : 0;
        __syncthreads();
        sm[tid] += t;
        __syncthreads();
    }
    if (tid < nb) g_boff[tid] = sm[tid] - v;
}
__global__ void rowptr_kernel(int N, int E) {
    int i = blockIdx.x * 256 + threadIdx.x;
    if (i < N) {
        int rp = g_scan[i] - g_deg[i] + g_boff[blockIdx.x];
        g_rowptr[i] = rp;
        g_cursor[i] = rp;
    }
    if (i == 0) g_rowptr[N] = E;
}
__global__ void scatter_kernel(const int* __restrict__ src,
                               const int* __restrict__ dst, int E, int N) {
    int e = blockIdx.x * blockDim.x + threadIdx.x;
    if (e >= E) return;
    int d = dst[e];
    int s = src[e];
    if ((unsigned)d >= (unsigned)N || (unsigned)s >= (unsigned)N) return;
    int pos = atomicAdd(&g_cursor[d], 1);
    g_csr_src[pos] = s;
}

// ================= aggregation (online softmax) =================
__device__ __forceinline__ void supd(float v, float t, float& m, float& den, float& acc) {
    float msg = fmaxf(v, 0.0f) + 1e-7f;
    float l = msg * t;
    if (l > m) { float c = __expf(m - l); den *= c; acc *= c; m = l; }
    float w = __expf(l - m);
    den += w;
    acc += w * msg;
}
__device__ __forceinline__ void pack_hl(const float* o, __half* H, __half* L,
                                        int gw, int lane) {
    __half2 h0 = __floats2half2_rn(o[0], o[1]);
    __half2 h1 = __floats2half2_rn(o[2], o[3]);
    __half2 l0 = __floats2half2_rn(o[0] - __low2float(h0), o[1] - __high2float(h0));
    __half2 l1 = __floats2half2_rn(o[2] - __low2float(h1), o[3] - __high2float(h1));
    uint2 uh, ul;
    uh.x = *(uint32_t*)&h0; uh.y = *(uint32_t*)&h1;
    ul.x = *(uint32_t*)&l0; ul.y = *(uint32_t*)&l1;
    ((uint2*)H)[gw * 32 + lane] = uh;
    ((uint2*)L)[gw * 32 + lane] = ul;
}
__device__ __forceinline__ void pack_f16(const float* o, __half* H, int gw, int lane) {
    __half2 p0 = __floats2half2_rn(o[0], o[1]);
    __half2 p1 = __floats2half2_rn(o[2], o[3]);
    uint2 u;
    u.x = *(uint32_t*)&p0;
    u.y = *(uint32_t*)&p1;
    ((uint2*)H)[gw * 32 + lane] = u;
}

__global__ void aggr_kernel(const float* __restrict__ x,
                            const float* __restrict__ t_all, int layer, int N) {
    int gw = (blockIdx.x * 256 + threadIdx.x) >> 5;
    int lane = threadIdx.x & 31;
    if (gw >= N) return;
    int beg = g_rowptr[gw], end = g_rowptr[gw + 1];
    float t = __ldg(&t_all[layer]);
    const float4* x4 = (const float4*)x;
    float m[4] = {-INFINITY, -INFINITY, -INFINITY, -INFINITY};
    float d[4] = {0, 0, 0, 0}, a[4] = {0, 0, 0, 0};
    int sj = (beg < end) ? g_csr_src[beg] : 0;
    for (int j = beg; j < end; j++) {
        int s = sj;
        if (j + 1 < end) sj = g_csr_src[j + 1];
        float4 v = __ldg(&x4[s * 32 + lane]);
        supd(v.x, t, m[0], d[0], a[0]);
        supd(v.y, t, m[1], d[1], a[1]);
        supd(v.z, t, m[2], d[2], a[2]);
        supd(v.w, t, m[3], d[3], a[3]);
    }
    float4 xv = __ldg(&x4[gw * 32 + lane]);
    float xc[4] = {xv.x, xv.y, xv.z, xv.w};
    float o[4];
#pragma unroll
    for (int ci = 0; ci < 4; ci++) o[ci] = a[ci] / (d[ci] + 1e-16f) + xc[ci];
    pack_hl(o, g_ahh, g_ahl, gw, lane);
}

__global__ void aggr_dual_kernel(const float* __restrict__ x,
                                 const float* __restrict__ t_all, int N) {
    int gw = (blockIdx.x * 256 + threadIdx.x) >> 5;
    int lane = threadIdx.x & 31;
    if (gw >= N) return;
    int beg = g_rowptr[gw], end = g_rowptr[gw + 1];
    float tA = __ldg(&t_all[2]);
    float tB = __ldg(&t_all[3]);
    const float4* x4 = (const float4*)x;
    float4 xv = __ldg(&x4[gw * 32 + lane]);
    float xc[4] = {xv.x, xv.y, xv.z, xv.w};

    if (tA == tB) {
        float m[4] = {-INFINITY, -INFINITY, -INFINITY, -INFINITY};
        float d[4] = {0, 0, 0, 0}, a[4] = {0, 0, 0, 0};
        int sj = (beg < end) ? g_csr_src[beg] : 0;
        for (int j = beg; j < end; j++) {
            int s = sj;
            if (j + 1 < end) sj = g_csr_src[j + 1];
            float4 v = __ldg(&x4[s * 32 + lane]);
            supd(v.x, tA, m[0], d[0], a[0]);
            supd(v.y, tA, m[1], d[1], a[1]);
            supd(v.z, tA, m[2], d[2], a[2]);
            supd(v.w, tA, m[3], d[3], a[3]);
        }
        float o[4];
#pragma unroll
        for (int ci = 0; ci < 4; ci++) o[ci] = a[ci] / (d[ci] + 1e-16f) + xc[ci];
        pack_f16(o, g_af16, gw, lane);
        pack_f16(o, g_af16b, gw, lane);
    } else {
        float mA[4] = {-INFINITY, -INFINITY, -INFINITY, -INFINITY};
        float dA[4] = {0, 0, 0, 0}, aA[4] = {0, 0, 0, 0};
        float mB[4] = {-INFINITY, -INFINITY, -INFINITY, -INFINITY};
        float dB[4] = {0, 0, 0, 0}, aB[4] = {0, 0, 0, 0};
        int sj = (beg < end) ? g_csr_src[beg] : 0;
        for (int j = beg; j < end; j++) {
            int s = sj;
            if (j + 1 < end) sj = g_csr_src[j + 1];
            float4 v = __ldg(&x4[s * 32 + lane]);
            float vv[4] = {v.x, v.y, v.z, v.w};
#pragma unroll
            for (int ci = 0; ci < 4; ci++) {
                supd(vv[ci], tA, mA[ci], dA[ci], aA[ci]);
                supd(vv[ci], tB, mB[ci], dB[ci], aB[ci]);
            }
        }
        float oA[4], oB[4];
#pragma unroll
        for (int ci = 0; ci < 4; ci++) {
            oA[ci] = aA[ci] / (dA[ci] + 1e-16f) + xc[ci];
            oB[ci] = aB[ci] / (dB[ci] + 1e-16f) + xc[ci];
        }
        pack_f16(oA, g_af16, gw, lane);
        pack_f16(oB, g_af16b, gw, lane);
    }
}

// ================= host orchestration =================
extern "C" void kernel_launch(void* const* d_in, const int* in_sizes, int n_in,
                              void* d_out, int out_size) {
    const float* x = (const float*)d_in[0];
    const int*   ei = (const int*)d_in[1];
    const float* t_all = (const float*)d_in[2];
    const float* W1 = (const float*)d_in[3];
    const float* W2 = (const float*)d_in[4];
    const float* gamma = (const float*)d_in[5];
    const float* beta = (const float*)d_in[6];

    const int N = in_sizes[0] / DD;
    const int E = in_sizes[1] / 2;
    const int* src = ei;
    const int* dst = ei + E;
    float* out = (float*)d_out;

    cudaFuncSetAttribute(gemm1_p3, cudaFuncAttributeMaxDynamicSharedMemorySize, 4 * CHSZ4);
    cudaFuncSetAttribute(gemm1_p2, cudaFuncAttributeMaxDynamicSharedMemorySize, 4 * CHSZ3);
    cudaFuncSetAttribute(gemm2_p3, cudaFuncAttributeMaxDynamicSharedMemorySize, 4 * CHSZ4);
    cudaFuncSetAttribute(gemm2_p2, cudaFuncAttributeMaxDynamicSharedMemorySize, 4 * CHSZ3);

    float* hA; cudaGetSymbolAddress((void**)&hA, g_hA);
    float* hB; cudaGetSymbolAddress((void**)&hB, g_hB);
    float* sS; cudaGetSymbolAddress((void**)&sS, g_statS);
    float* sQ; cudaGetSymbolAddress((void**)&sQ, g_statQ);
    __half *h1h, *h1l, *h1f, *h1fb;
    cudaGetSymbolAddress((void**)&h1h, g_h1h);
    cudaGetSymbolAddress((void**)&h1l, g_h1l);
    cudaGetSymbolAddress((void**)&h1f, g_h1f);
    cudaGetSymbolAddress((void**)&h1fb, g_h1fb);
    __half *ahh, *ahl, *af, *afb, *w1h, *w1l, *w2h, *w2l;
    cudaGetSymbolAddress((void**)&ahh, g_ahh);
    cudaGetSymbolAddress((void**)&ahl, g_ahl);
    cudaGetSymbolAddress((void**)&af, g_af16);
    cudaGetSymbolAddress((void**)&afb, g_af16b);
    cudaGetSymbolAddress((void**)&w1h, g_w1h);
    cudaGetSymbolAddress((void**)&w1l, g_w1l);
    cudaGetSymbolAddress((void**)&w2h, g_w2h);
    cudaGetSymbolAddress((void**)&w2l, g_w2l);

    const int mtiles = (N + 127) / 128;

    pack_w_kernel<<<1024, 256>>>(W1, W2, N);
    hist_kernel<<<(E + 255) / 256, 256>>>(dst, E, N);
    blockscan_kernel<<<NB, 256>>>(N);
    scanbsum_kernel<<<1, 512>>>(NB);
    rowptr_kernel<<<NB, 256>>>(N, E);
    scatter_kernel<<<(E + 255) / 256, 256>>>(src, dst, E, N);

    const int AG = (N * 32 + 255) / 256;

    // ---- layer 0 ----
    aggr_kernel<<<AG, 256>>>(x, t_all, 0, N);
    gemm1_p3<<<dim3(2, mtiles), 256, 4 * CHSZ4>>>(
        ahh, ahl, w1h + 0 * 32768, w1l + 0 * 32768, h1h, h1l,
        sS + 0 * DD2, sQ + 0 * DD2, N);
    gemm2_p3<<<dim3(1, mtiles), 256, 4 * CHSZ4>>>(
        h1h, h1l, w2h + 0 * 32768, w2l + 0 * 32768, hA, gamma, beta, 0, N);
    // ---- layer 1 ----
    aggr_kernel<<<AG, 256>>>(hA, t_all, 1, N);
    gemm1_p3<<<dim3(2, mtiles), 256, 4 * CHSZ4>>>(
        ahh, ahl, w1h + 1 * 32768, w1l + 1 * 32768, h1h, h1l,
        sS + 1 * DD2, sQ + 1 * DD2, N);
    gemm2_p3<<<dim3(1, mtiles), 256, 4 * CHSZ4>>>(
        h1h, h1l, w2h + 1 * 32768, w2l + 1 * 32768, hB, gamma, beta, 1, N);
    // ---- layers 2 & 3 (mu, logstd): 2-pass, z-batched ----
    aggr_dual_kernel<<<AG, 256>>>(hB, t_all, N);
    gemm1_p2<<<dim3(2, mtiles, 2), 256, 4 * CHSZ3>>>(
        af, afb, w1h + 2 * 32768, w1l + 2 * 32768, h1f, h1fb,
        sS + 2 * DD2, sQ + 2 * DD2, N);
    gemm2_p2<<<dim3(1, mtiles, 2), 256, 4 * CHSZ3>>>(
        h1f, h1fb, w2h + 2 * 32768, w2l + 2 * 32768, out, out + (size_t)N * DD,
        gamma, beta, 2, N);
}

// round 14
// speedup vs baseline: 1.0584x; 1.0584x over previous
#include <cuda_runtime.h>
#include <cuda_fp16.h>
#include <math.h>
#include <stdint.h>

#define NN 100000
#define NPAD 100128
#define DD 128
#define DD2 256
#define EE 800000
#define NB ((NN + 255) / 256)
#define STRD 48          // k16 chunk: 16 elems*2B = 32B + 16B pad -> LDSM conflict-free
#define SEG 6144         // 128*48
#define CHSZ3 18432      // 3 segments (A, B_hi, B_lo)
#define CHSZ4 24576      // 4 segments (A_hi, A_lo, B_hi, B_lo)

// ================= scratch =================
__device__ float g_hA[NN * DD];
__device__ float g_hB[NN * DD];
__device__ float g_h1[NN * DD2];
__device__ float g_h1b[NN * DD2];
__device__ float g_statS[4 * DD2];
__device__ float g_statQ[4 * DD2];
__device__ int   g_dualsame;                           // t_all[2]==t_all[3] flag
__device__ __align__(256) __half g_ahh[NPAD * DD];   // aggr out hi (layers 0,1)
__device__ __align__(256) __half g_ahl[NPAD * DD];   // aggr out lo
__device__ __align__(256) __half g_af16[NPAD * DD];  // aggr out single fp16 (layer 2)
__device__ __align__(256) __half g_af16b[NPAD * DD]; // (layer 3; unused if dualsame)
__device__ __align__(256) __half g_w1h[4 * 256 * 128];  // [l][n][k] fp16 hi
__device__ __align__(256) __half g_w1l[4 * 256 * 128];
__device__ __align__(256) __half g_w2h[4 * 128 * 256];  // [l][n][k] fp16 hi
__device__ __align__(256) __half g_w2l[4 * 128 * 256];
__device__ int g_deg[NN];
__device__ int g_scan[NN];
__device__ int g_bsum[512];
__device__ int g_boff[512];
__device__ int g_rowptr[NN + 1];
__device__ int g_cursor[NN];
__device__ int g_csr_src[EE];

// ================= small helpers =================
__device__ __forceinline__ uint32_t smem_u32(const void* p) {
    uint32_t a;
    asm("{ .reg .u64 t; cvta.to.shared.u64 t, %1; cvt.u32.u64 %0, t; }"
        : "=r"(a) : "l"(p));
    return a;
}
#define CP_ASYNC16(sa, ga) \
    asm volatile("cp.async.cg.shared.global [%0], [%1], 16;" :: "r"(sa), "l"(ga))
#define CP_COMMIT() asm volatile("cp.async.commit_group;")
#define CP_WAIT0() asm volatile("cp.async.wait_group 0;")
#define CP_WAIT1() asm volatile("cp.async.wait_group 1;")
#define CP_WAIT2() asm volatile("cp.async.wait_group 2;")

__device__ __forceinline__ void ldsm_x4(uint32_t* r, uint32_t addr) {
    asm volatile("ldmatrix.sync.aligned.m8n8.x4.shared.b16 {%0,%1,%2,%3}, [%4];"
                 : "=r"(r[0]), "=r"(r[1]), "=r"(r[2]), "=r"(r[3]) : "r"(addr));
}
__device__ __forceinline__ void mma_f16(float* c, const uint32_t* a, const uint32_t* b) {
    asm volatile(
        "mma.sync.aligned.m16n8k16.row.col.f32.f16.f16.f32 "
        "{%0,%1,%2,%3}, {%4,%5,%6,%7}, {%8,%9}, {%0,%1,%2,%3};"
        : "+f"(c[0]), "+f"(c[1]), "+f"(c[2]), "+f"(c[3])
        : "r"(a[0]), "r"(a[1]), "r"(a[2]), "r"(a[3]), "r"(b[0]), "r"(b[1]));
}

// ---- 2-pass chunk: segs [A, Bh, Bl]; C += A*Bh + A*Bl. 10 LDSM + 32 MMA ----
__device__ __forceinline__ void mma_chunk2(uint32_t buf, int wm, int wn, int g, int r,
                                           float c[2][8][4]) {
    uint32_t a[2][4], bf[16];
    uint32_t acol = (uint32_t)(g >> 1) * 16;
    uint32_t bcol = (uint32_t)(g & 1) * 16;
#pragma unroll
    for (int mt = 0; mt < 2; mt++) {
        uint32_t arow = (uint32_t)(wm + mt * 16 + (g & 1) * 8 + r);
        ldsm_x4(a[mt], buf + arow * STRD + acol);
    }
#pragma unroll
    for (int nb = 0; nb < 4; nb++) {
        uint32_t brow = (uint32_t)(wn + nb * 16 + (g >> 1) * 8 + r);
        ldsm_x4(&bf[nb * 4], buf + SEG + brow * STRD + bcol);
    }
#pragma unroll
    for (int mt = 0; mt < 2; mt++)
#pragma unroll
        for (int nt = 0; nt < 8; nt++) mma_f16(c[mt][nt], a[mt], &bf[nt * 2]);
#pragma unroll
    for (int nb = 0; nb < 4; nb++) {
        uint32_t brow = (uint32_t)(wn + nb * 16 + (g >> 1) * 8 + r);
        ldsm_x4(&bf[nb * 4], buf + 2 * SEG + brow * STRD + bcol);
    }
#pragma unroll
    for (int mt = 0; mt < 2; mt++)
#pragma unroll
        for (int nt = 0; nt < 8; nt++) mma_f16(c[mt][nt], a[mt], &bf[nt * 2]);
}

// ---- 3-pass chunk: segs [Ah, Al, Bh, Bl]; C += Ah*Bh + Al*Bh + Ah*Bl ----
__device__ __forceinline__ void mma_chunk3(uint32_t buf, int wm, int wn, int g, int r,
                                           float c[2][8][4]) {
    uint32_t ah[2][4], al[2][4], bf[16];
    uint32_t acol = (uint32_t)(g >> 1) * 16;
    uint32_t bcol = (uint32_t)(g & 1) * 16;
#pragma unroll
    for (int mt = 0; mt < 2; mt++) {
        uint32_t arow = (uint32_t)(wm + mt * 16 + (g & 1) * 8 + r);
        ldsm_x4(ah[mt], buf + arow * STRD + acol);
        ldsm_x4(al[mt], buf + SEG + arow * STRD + acol);
    }
#pragma unroll
    for (int nb = 0; nb < 4; nb++) {
        uint32_t brow = (uint32_t)(wn + nb * 16 + (g >> 1) * 8 + r);
        ldsm_x4(&bf[nb * 4], buf + 2 * SEG + brow * STRD + bcol);
    }
#pragma unroll
    for (int mt = 0; mt < 2; mt++)
#pragma unroll
        for (int nt = 0; nt < 8; nt++) mma_f16(c[mt][nt], ah[mt], &bf[nt * 2]);
#pragma unroll
    for (int mt = 0; mt < 2; mt++)
#pragma unroll
        for (int nt = 0; nt < 8; nt++) mma_f16(c[mt][nt], al[mt], &bf[nt * 2]);
#pragma unroll
    for (int nb = 0; nb < 4; nb++) {
        uint32_t brow = (uint32_t)(wn + nb * 16 + (g >> 1) * 8 + r);
        ldsm_x4(&bf[nb * 4], buf + 3 * SEG + brow * STRD + bcol);
    }
#pragma unroll
    for (int mt = 0; mt < 2; mt++)
#pragma unroll
        for (int nt = 0; nt < 8; nt++) mma_f16(c[mt][nt], ah[mt], &bf[nt * 2]);
}

// cp.async one segment: 128 rows x 32B/row
template <typename T>
__device__ __forceinline__ void seg_cp(uint32_t sm, const T* gsrc,
                                       int row0g, int ldk, int k0, int tid) {
    int m = tid >> 1, sub = tid & 1;
    uint32_t sa = sm + m * STRD + sub * 16;
    const void* ga = gsrc + (size_t)(row0g + m) * ldk + k0 + sub * 8;
    CP_ASYNC16(sa, ga);
}

// ---- shared epilogue pieces ----
__device__ __forceinline__ void store_c(float c[2][8][4], float* C, int row0, int col0,
                                        int NOUT, int wm, int wn, int lane, int M,
                                        bool relu) {
#pragma unroll
    for (int mt = 0; mt < 2; mt++) {
        int rb = row0 + wm + mt * 16 + (lane >> 2);
#pragma unroll
        for (int nt = 0; nt < 8; nt++) {
            int cb = col0 + wn + nt * 8 + (lane & 3) * 2;
            float2 v0 = make_float2(c[mt][nt][0], c[mt][nt][1]);
            float2 v1 = make_float2(c[mt][nt][2], c[mt][nt][3]);
            if (relu) {
                v0.x = fmaxf(v0.x, 0.f); v0.y = fmaxf(v0.y, 0.f);
                v1.x = fmaxf(v1.x, 0.f); v1.y = fmaxf(v1.y, 0.f);
            }
            if (rb < M)     *(float2*)&C[(size_t)rb * NOUT + cb] = v0;
            if (rb + 8 < M) *(float2*)&C[(size_t)(rb + 8) * NOUT + cb] = v1;
        }
    }
}
__device__ __forceinline__ void bn_stats_epi(float c[2][8][4], float* statS, float* statQ,
                                             int col0, int wn, int lane) {
    float s16[16], q16[16];
#pragma unroll
    for (int nt = 0; nt < 8; nt++)
#pragma unroll
        for (int j = 0; j < 2; j++) {
            float a0 = c[0][nt][j], a1 = c[0][nt][j + 2];
            float a2 = c[1][nt][j], a3 = c[1][nt][j + 2];
            s16[nt * 2 + j] = a0 + a1 + a2 + a3;
            q16[nt * 2 + j] = a0 * a0 + a1 * a1 + a2 * a2 + a3 * a3;
        }
#pragma unroll
    for (int i = 0; i < 16; i++) {
#pragma unroll
        for (int off = 4; off < 32; off <<= 1) {
            s16[i] += __shfl_xor_sync(0xffffffffu, s16[i], off);
            q16[i] += __shfl_xor_sync(0xffffffffu, q16[i], off);
        }
    }
    if ((lane >> 2) == 0) {
#pragma unroll
        for (int nt = 0; nt < 8; nt++)
#pragma unroll
            for (int j = 0; j < 2; j++) {
                int col = col0 + wn + nt * 8 + (lane & 3) * 2 + j;
                atomicAdd(&statS[col], s16[nt * 2 + j]);
                atomicAdd(&statQ[col], q16[nt * 2 + j]);
            }
    }
}

// ===== GEMM1 3-pass (layers 0,1): A hi/lo fp16 x B hi/lo, fused BN stats =====
__global__ void __launch_bounds__(256, 2)
gemm1_p3(const __half* __restrict__ Ah, const __half* __restrict__ Al,
         const __half* __restrict__ Bh, const __half* __restrict__ Bl,
         float* __restrict__ C, float* __restrict__ statS, float* __restrict__ statQ,
         int M) {
    extern __shared__ __align__(128) char dsm[];
    const uint32_t base = smem_u32(dsm);
    constexpr int KTOT = 128, NOUT = 256, NC = 8;

    int tid = threadIdx.x;
    int wid = tid >> 5, lane = tid & 31;
    int wm = (wid & 3) * 32, wn = (wid >> 2) * 64;
    int row0 = blockIdx.y * 128, col0 = blockIdx.x * 128;
    int g = lane >> 3, r = lane & 7;

    float c[2][8][4];
#pragma unroll
    for (int i = 0; i < 2; i++)
#pragma unroll
        for (int j = 0; j < 8; j++)
#pragma unroll
            for (int q = 0; q < 4; q++) c[i][j][q] = 0.0f;

    auto stage = [&](int ch) {
        uint32_t b = base + (ch & 3) * CHSZ4;
        int k0 = ch * 16;
        seg_cp(b + 0 * SEG, Ah, row0, KTOT, k0, tid);
        seg_cp(b + 1 * SEG, Al, row0, KTOT, k0, tid);
        seg_cp(b + 2 * SEG, Bh, col0, KTOT, k0, tid);
        seg_cp(b + 3 * SEG, Bl, col0, KTOT, k0, tid);
        CP_COMMIT();
    };

    stage(0); stage(1); stage(2);

#pragma unroll 1
    for (int ch = 0; ch < NC - 3; ch++) {
        CP_WAIT2();
        __syncthreads();
        stage(ch + 3);
        mma_chunk3(base + (ch & 3) * CHSZ4, wm, wn, g, r, c);
    }
    CP_WAIT2(); __syncthreads();
    mma_chunk3(base + ((NC - 3) & 3) * CHSZ4, wm, wn, g, r, c);
    CP_WAIT1(); __syncthreads();
    mma_chunk3(base + ((NC - 2) & 3) * CHSZ4, wm, wn, g, r, c);
    CP_WAIT0(); __syncthreads();
    mma_chunk3(base + ((NC - 1) & 3) * CHSZ4, wm, wn, g, r, c);

    store_c(c, C, row0, col0, NOUT, wm, wn, lane, M, false);
    bn_stats_epi(c, statS, statQ, col0, wn, lane);
}

// ===== GEMM1 2-pass (layers 2,3 z-batched): single-fp16 A x B hi/lo =====
__global__ void __launch_bounds__(256, 2)
gemm1_p2(const __half* __restrict__ A0, const __half* __restrict__ A1,
         const __half* __restrict__ Bh_base, const __half* __restrict__ Bl_base,
         float* __restrict__ C0, float* __restrict__ C1,
         float* __restrict__ statS_base, float* __restrict__ statQ_base, int M) {
    extern __shared__ __align__(128) char dsm[];
    const uint32_t base = smem_u32(dsm);
    constexpr int KTOT = 128, NOUT = 256, NC = 8;

    int z = blockIdx.z;
    const __half* Af = (z && !g_dualsame) ? A1 : A0;   // dedup when t2==t3
    const __half* Bh = Bh_base + (size_t)z * KTOT * NOUT;
    const __half* Bl = Bl_base + (size_t)z * KTOT * NOUT;
    float* C = z ? C1 : C0;

    int tid = threadIdx.x;
    int wid = tid >> 5, lane = tid & 31;
    int wm = (wid & 3) * 32, wn = (wid >> 2) * 64;
    int row0 = blockIdx.y * 128, col0 = blockIdx.x * 128;
    int g = lane >> 3, r = lane & 7;

    float c[2][8][4];
#pragma unroll
    for (int i = 0; i < 2; i++)
#pragma unroll
        for (int j = 0; j < 8; j++)
#pragma unroll
            for (int q = 0; q < 4; q++) c[i][j][q] = 0.0f;

    auto stage = [&](int ch) {
        uint32_t b = base + (ch & 3) * CHSZ3;
        int k0 = ch * 16;
        seg_cp(b + 0 * SEG, Af, row0, KTOT, k0, tid);
        seg_cp(b + 1 * SEG, Bh, col0, KTOT, k0, tid);
        seg_cp(b + 2 * SEG, Bl, col0, KTOT, k0, tid);
        CP_COMMIT();
    };

    stage(0); stage(1); stage(2);

#pragma unroll 1
    for (int ch = 0; ch < NC - 3; ch++) {
        CP_WAIT2();
        __syncthreads();
        stage(ch + 3);
        mma_chunk2(base + (ch & 3) * CHSZ3, wm, wn, g, r, c);
    }
    CP_WAIT2(); __syncthreads();
    mma_chunk2(base + ((NC - 3) & 3) * CHSZ3, wm, wn, g, r, c);
    CP_WAIT1(); __syncthreads();
    mma_chunk2(base + ((NC - 2) & 3) * CHSZ3, wm, wn, g, r, c);
    CP_WAIT0(); __syncthreads();
    mma_chunk2(base + ((NC - 1) & 3) * CHSZ3, wm, wn, g, r, c);

    store_c(c, C, row0, col0, NOUT, wm, wn, lane, M, false);
    bn_stats_epi(c, statS_base + z * DD2, statQ_base + z * DD2, col0, wn, lane);
}

// ===== GEMM2 3-pass (layers 0,1): fp32 A + fused-BN prolog -> fp16 hi/lo =====
__global__ void __launch_bounds__(256, 2)
gemm2_p3(const float* __restrict__ Af,
         const __half* __restrict__ Bh, const __half* __restrict__ Bl,
         float* __restrict__ C,
         const float* __restrict__ gamma, const float* __restrict__ beta,
         int l, int M) {
    extern __shared__ __align__(128) char dsm[];
    __shared__ float s_scale[DD2];
    __shared__ float s_shift[DD2];
    const uint32_t base = smem_u32(dsm);
    constexpr int KTOT = 256, NOUT = 128, NC = 16;

    int tid = threadIdx.x;
    int wid = tid >> 5, lane = tid & 31;
    int wm = (wid & 3) * 32, wn = (wid >> 2) * 64;
    int row0 = blockIdx.y * 128;
    int g = lane >> 3, r = lane & 7;

    {
        int cc = tid;
        float s = g_statS[l * DD2 + cc];
        float q = g_statQ[l * DD2 + cc];
        float mean = s / (float)M;
        float var = q / (float)M - mean * mean;
        float inv = rsqrtf(var + 1e-5f);
        float sc = inv * gamma[l * DD2 + cc];
        s_scale[cc] = sc;
        s_shift[cc] = beta[l * DD2 + cc] - mean * sc;
    }
    __syncthreads();

    float c[2][8][4];
#pragma unroll
    for (int i = 0; i < 2; i++)
#pragma unroll
        for (int j = 0; j < 8; j++)
#pragma unroll
            for (int q = 0; q < 4; q++) c[i][j][q] = 0.0f;

    int am = tid >> 1;
    int asub = tid & 1;
    float av[8];

    auto stageB = [&](int ch) {
        uint32_t b = base + (ch & 1) * CHSZ4;
        int k0 = ch * 16;
        seg_cp(b + 2 * SEG, Bh, 0, KTOT, k0, tid);
        seg_cp(b + 3 * SEG, Bl, 0, KTOT, k0, tid);
        CP_COMMIT();
    };
    auto ldgA = [&](int ch) {
        int row = row0 + am;
        int k0 = ch * 16 + asub * 8;
        if (row < M) {
            float4 u0 = *(const float4*)&Af[(size_t)row * KTOT + k0];
            float4 u1 = *(const float4*)&Af[(size_t)row * KTOT + k0 + 4];
            av[0]=u0.x; av[1]=u0.y; av[2]=u0.z; av[3]=u0.w;
            av[4]=u1.x; av[5]=u1.y; av[6]=u1.z; av[7]=u1.w;
        } else {
#pragma unroll
            for (int p = 0; p < 8; p++) av[p] = 0.f;
        }
    };
    auto stsA = [&](int ch) {
        uint32_t b = base + (ch & 1) * CHSZ4;
        int k0 = ch * 16 + asub * 8;
        uint32_t hp[4], lp[4];
#pragma unroll
        for (int p = 0; p < 4; p++) {
            float a0 = fmaxf(av[2*p]   * s_scale[k0 + 2*p]   + s_shift[k0 + 2*p],   0.f);
            float a1 = fmaxf(av[2*p+1] * s_scale[k0 + 2*p+1] + s_shift[k0 + 2*p+1], 0.f);
            __half2 hh = __floats2half2_rn(a0, a1);
            __half2 ll = __floats2half2_rn(a0 - __half2float(__low2half(hh)),
                                           a1 - __half2float(__high2half(hh)));
            hp[p] = *(uint32_t*)&hh;
            lp[p] = *(uint32_t*)&ll;
        }
        uint32_t off = (b - base) + am * STRD + asub * 16;
        *(uint4*)(dsm + off)       = make_uint4(hp[0], hp[1], hp[2], hp[3]);
        *(uint4*)(dsm + SEG + off) = make_uint4(lp[0], lp[1], lp[2], lp[3]);
    };

    stageB(0);
    ldgA(0);
    stsA(0);
    ldgA(1);
    CP_WAIT0();
    __syncthreads();

#pragma unroll 1
    for (int ch = 0; ch < NC; ch++) {
        bool hn = (ch + 1 < NC);
        if (hn) { stageB(ch + 1); stsA(ch + 1); }
        if (ch + 2 < NC) ldgA(ch + 2);
        mma_chunk3(base + (ch & 1) * CHSZ4, wm, wn, g, r, c);
        if (hn) CP_WAIT0();
        __syncthreads();
    }

    store_c(c, C, row0, 0, NOUT, wm, wn, lane, M, true);
}

// ===== GEMM2 2-pass (final mu/logstd, z-batched): single-fp16 A prolog =====
__global__ void __launch_bounds__(256, 2)
gemm2_p2(const float* __restrict__ A0, const float* __restrict__ A1,
         const __half* __restrict__ Bh_base, const __half* __restrict__ Bl_base,
         float* __restrict__ C0, float* __restrict__ C1,
         const float* __restrict__ gamma, const float* __restrict__ beta,
         int layer0, int M) {
    extern __shared__ __align__(128) char dsm[];
    __shared__ float s_scale[DD2];
    __shared__ float s_shift[DD2];
    const uint32_t base = smem_u32(dsm);
    constexpr int KTOT = 256, NOUT = 128, NC = 16;

    int z = blockIdx.z;
    int l = layer0 + z;
    const float* Af = z ? A1 : A0;
    const __half* Bh = Bh_base + (size_t)z * KTOT * NOUT;
    const __half* Bl = Bl_base + (size_t)z * KTOT * NOUT;
    float* C = z ? C1 : C0;

    int tid = threadIdx.x;
    int wid = tid >> 5, lane = tid & 31;
    int wm = (wid & 3) * 32, wn = (wid >> 2) * 64;
    int row0 = blockIdx.y * 128;
    int g = lane >> 3, r = lane & 7;

    {
        int cc = tid;
        float s = g_statS[l * DD2 + cc];
        float q = g_statQ[l * DD2 + cc];
        float mean = s / (float)M;
        float var = q / (float)M - mean * mean;
        float inv = rsqrtf(var + 1e-5f);
        float sc = inv * gamma[l * DD2 + cc];
        s_scale[cc] = sc;
        s_shift[cc] = beta[l * DD2 + cc] - mean * sc;
    }
    __syncthreads();

    float c[2][8][4];
#pragma unroll
    for (int i = 0; i < 2; i++)
#pragma unroll
        for (int j = 0; j < 8; j++)
#pragma unroll
            for (int q = 0; q < 4; q++) c[i][j][q] = 0.0f;

    int am = tid >> 1;
    int asub = tid & 1;
    float av[8];

    auto stageB = [&](int ch) {
        uint32_t b = base + (ch & 1) * CHSZ3;
        int k0 = ch * 16;
        seg_cp(b + 1 * SEG, Bh, 0, KTOT, k0, tid);
        seg_cp(b + 2 * SEG, Bl, 0, KTOT, k0, tid);
        CP_COMMIT();
    };
    auto ldgA = [&](int ch) {
        int row = row0 + am;
        int k0 = ch * 16 + asub * 8;
        if (row < M) {
            float4 u0 = *(const float4*)&Af[(size_t)row * KTOT + k0];
            float4 u1 = *(const float4*)&Af[(size_t)row * KTOT + k0 + 4];
            av[0]=u0.x; av[1]=u0.y; av[2]=u0.z; av[3]=u0.w;
            av[4]=u1.x; av[5]=u1.y; av[6]=u1.z; av[7]=u1.w;
        } else {
#pragma unroll
            for (int p = 0; p < 8; p++) av[p] = 0.f;
        }
    };
    auto stsA = [&](int ch) {
        uint32_t b = base + (ch & 1) * CHSZ3;
        int k0 = ch * 16 + asub * 8;
        uint32_t hp[4];
#pragma unroll
        for (int p = 0; p < 4; p++) {
            float a0 = fmaxf(av[2*p]   * s_scale[k0 + 2*p]   + s_shift[k0 + 2*p],   0.f);
            float a1 = fmaxf(av[2*p+1] * s_scale[k0 + 2*p+1] + s_shift[k0 + 2*p+1], 0.f);
            __half2 hh = __floats2half2_rn(a0, a1);
            hp[p] = *(uint32_t*)&hh;
        }
        uint32_t off = (b - base) + am * STRD + asub * 16;
        *(uint4*)(dsm + off) = make_uint4(hp[0], hp[1], hp[2], hp[3]);
    };

    stageB(0);
    ldgA(0);
    stsA(0);
    ldgA(1);
    CP_WAIT0();
    __syncthreads();

#pragma unroll 1
    for (int ch = 0; ch < NC; ch++) {
        bool hn = (ch + 1 < NC);
        if (hn) { stageB(ch + 1); stsA(ch + 1); }
        if (ch + 2 < NC) ldgA(ch + 2);
        mma_chunk2(base + (ch & 1) * CHSZ3, wm, wn, g, r, c);
        if (hn) CP_WAIT0();
        __syncthreads();
    }

    store_c(c, C, row0, 0, NOUT, wm, wn, lane, M, false);
}

// ===== weight pack (W1, W2 fp16 hi/lo) + zero stats/deg =====
__global__ void pack_w_kernel(const float* __restrict__ W1, const float* __restrict__ W2,
                              int N) {
    int idx = blockIdx.x * blockDim.x + threadIdx.x;
    if (idx < 131072) {
        int l = idx >> 15, rr = idx & 32767;
        int k = rr >> 8, n = rr & 255;
        float v = W1[(size_t)l * 32768 + rr];
        __half h = __float2half_rn(v);
        __half lo = __float2half_rn(v - __half2float(h));
        int o = l * 32768 + n * 128 + k;
        g_w1h[o] = h; g_w1l[o] = lo;
    } else if (idx < 262144) {
        int j = idx - 131072;
        int l = j >> 15, rr = j & 32767;
        int k = rr >> 7, n = rr & 127;
        float v = W2[(size_t)l * 32768 + rr];
        __half h = __float2half_rn(v);
        __half lo = __float2half_rn(v - __half2float(h));
        int o = l * 32768 + n * 256 + k;
        g_w2h[o] = h; g_w2l[o] = lo;
    }
    if (idx < 1024) { g_statS[idx] = 0.f; g_statQ[idx] = 0.f; }
    if (idx < N) g_deg[idx] = 0;
}

// ================= CSR build =================
__global__ void hist_kernel(const int* __restrict__ dst, int E, int N) {
    int e = blockIdx.x * blockDim.x + threadIdx.x;
    if (e >= E) return;
    int d = dst[e];
    if ((unsigned)d < (unsigned)N) atomicAdd(&g_deg[d], 1);
}
__global__ void blockscan_kernel(int N) {
    __shared__ int sm[256];
    int i = blockIdx.x * 256 + threadIdx.x;
    int v = (i < N) ? g_deg[i] : 0;
    sm[threadIdx.x] = v;
    __syncthreads();
#pragma unroll
    for (int off = 1; off < 256; off <<= 1) {
        int t = (threadIdx.x >= off) ? sm[threadIdx.x - off] : 0;
        __syncthreads();
        sm[threadIdx.x] += t;
        __syncthreads();
    }
    if (i < N) g_scan[i] = sm[threadIdx.x];
    if (threadIdx.x == 255) g_bsum[blockIdx.x] = sm[255];
}
__global__ void scanbsum_kernel(int nb) {
    __shared__ int sm[512];
    int tid = threadIdx.x;
    int v = (tid < nb) ? g_bsum[tid] : 0;
    sm[tid] = v;
    __syncthreads();
#pragma unroll
    for (int off = 1; off < 512; off <<= 1) {
        int t = (tid >= off) ? sm[tid - off] : 0;
        __syncthreads();
        sm[tid] += t;
        __syncthreads();
    }
    if (tid < nb) g_boff[tid] = sm[tid] - v;
}
__global__ void rowptr_kernel(int N, int E) {
    int i = blockIdx.x * 256 + threadIdx.x;
    if (i < N) {
        int rp = g_scan[i] - g_deg[i] + g_boff[blockIdx.x];
        g_rowptr[i] = rp;
        g_cursor[i] = rp;
    }
    if (i == 0) g_rowptr[N] = E;
}
__global__ void scatter_kernel(const int* __restrict__ src,
                               const int* __restrict__ dst, int E, int N) {
    int e = blockIdx.x * blockDim.x + threadIdx.x;
    if (e >= E) return;
    int d = dst[e];
    int s = src[e];
    if ((unsigned)d >= (unsigned)N || (unsigned)s >= (unsigned)N) return;
    int pos = atomicAdd(&g_cursor[d], 1);
    g_csr_src[pos] = s;
}

// ================= aggregation (online softmax) =================
__device__ __forceinline__ void supd(float v, float t, float& m, float& den, float& acc) {
    float msg = fmaxf(v, 0.0f) + 1e-7f;
    float l = msg * t;
    if (l > m) { float c = __expf(m - l); den *= c; acc *= c; m = l; }
    float w = __expf(l - m);
    den += w;
    acc += w * msg;
}
__device__ __forceinline__ void pack_hl(const float* o, __half* H, __half* L,
                                        int gw, int lane) {
    __half2 h0 = __floats2half2_rn(o[0], o[1]);
    __half2 h1 = __floats2half2_rn(o[2], o[3]);
    __half2 l0 = __floats2half2_rn(o[0] - __low2float(h0), o[1] - __high2float(h0));
    __half2 l1 = __floats2half2_rn(o[2] - __low2float(h1), o[3] - __high2float(h1));
    uint2 uh, ul;
    uh.x = *(uint32_t*)&h0; uh.y = *(uint32_t*)&h1;
    ul.x = *(uint32_t*)&l0; ul.y = *(uint32_t*)&l1;
    ((uint2*)H)[gw * 32 + lane] = uh;
    ((uint2*)L)[gw * 32 + lane] = ul;
}
__device__ __forceinline__ void pack_f16(const float* o, __half* H, int gw, int lane) {
    __half2 p0 = __floats2half2_rn(o[0], o[1]);
    __half2 p1 = __floats2half2_rn(o[2], o[3]);
    uint2 u;
    u.x = *(uint32_t*)&p0;
    u.y = *(uint32_t*)&p1;
    ((uint2*)H)[gw * 32 + lane] = u;
}

__global__ void aggr_kernel(const float* __restrict__ x,
                            const float* __restrict__ t_all, int layer, int N) {
    int gw = (blockIdx.x * 256 + threadIdx.x) >> 5;
    int lane = threadIdx.x & 31;
    if (gw >= N) return;
    int beg = g_rowptr[gw], end = g_rowptr[gw + 1];
    float t = __ldg(&t_all[layer]);
    const float4* x4 = (const float4*)x;
    float m[4] = {-INFINITY, -INFINITY, -INFINITY, -INFINITY};
    float d[4] = {0, 0, 0, 0}, a[4] = {0, 0, 0, 0};
    int sj = (beg < end) ? g_csr_src[beg] : 0;
    for (int j = beg; j < end; j++) {
        int s = sj;
        if (j + 1 < end) sj = g_csr_src[j + 1];
        float4 v = __ldg(&x4[s * 32 + lane]);
        supd(v.x, t, m[0], d[0], a[0]);
        supd(v.y, t, m[1], d[1], a[1]);
        supd(v.z, t, m[2], d[2], a[2]);
        supd(v.w, t, m[3], d[3], a[3]);
    }
    float4 xv = __ldg(&x4[gw * 32 + lane]);
    float xc[4] = {xv.x, xv.y, xv.z, xv.w};
    float o[4];
#pragma unroll
    for (int ci = 0; ci < 4; ci++) o[ci] = a[ci] / (d[ci] + 1e-16f) + xc[ci];
    pack_hl(o, g_ahh, g_ahl, gw, lane);
}

__global__ void aggr_dual_kernel(const float* __restrict__ x,
                                 const float* __restrict__ t_all, int N) {
    int gw = (blockIdx.x * 256 + threadIdx.x) >> 5;
    int lane = threadIdx.x & 31;
    if (gw >= N) return;
    int beg = g_rowptr[gw], end = g_rowptr[gw + 1];
    float tA = __ldg(&t_all[2]);
    float tB = __ldg(&t_all[3]);
    const float4* x4 = (const float4*)x;
    float4 xv = __ldg(&x4[gw * 32 + lane]);
    float xc[4] = {xv.x, xv.y, xv.z, xv.w};

    if (tA == tB) {
        if (gw == 0 && lane == 0) g_dualsame = 1;
        float m[4] = {-INFINITY, -INFINITY, -INFINITY, -INFINITY};
        float d[4] = {0, 0, 0, 0}, a[4] = {0, 0, 0, 0};
        int sj = (beg < end) ? g_csr_src[beg] : 0;
        for (int j = beg; j < end; j++) {
            int s = sj;
            if (j + 1 < end) sj = g_csr_src[j + 1];
            float4 v = __ldg(&x4[s * 32 + lane]);
            supd(v.x, tA, m[0], d[0], a[0]);
            supd(v.y, tA, m[1], d[1], a[1]);
            supd(v.z, tA, m[2], d[2], a[2]);
            supd(v.w, tA, m[3], d[3], a[3]);
        }
        float o[4];
#pragma unroll
        for (int ci = 0; ci < 4; ci++) o[ci] = a[ci] / (d[ci] + 1e-16f) + xc[ci];
        pack_f16(o, g_af16, gw, lane);   // single copy; consumers dedup via flag
    } else {
        if (gw == 0 && lane == 0) g_dualsame = 0;
        float mA[4] = {-INFINITY, -INFINITY, -INFINITY, -INFINITY};
        float dA[4] = {0, 0, 0, 0}, aA[4] = {0, 0, 0, 0};
        float mB[4] = {-INFINITY, -INFINITY, -INFINITY, -INFINITY};
        float dB[4] = {0, 0, 0, 0}, aB[4] = {0, 0, 0, 0};
        int sj = (beg < end) ? g_csr_src[beg] : 0;
        for (int j = beg; j < end; j++) {
            int s = sj;
            if (j + 1 < end) sj = g_csr_src[j + 1];
            float4 v = __ldg(&x4[s * 32 + lane]);
            float vv[4] = {v.x, v.y, v.z, v.w};
#pragma unroll
            for (int ci = 0; ci < 4; ci++) {
                supd(vv[ci], tA, mA[ci], dA[ci], aA[ci]);
                supd(vv[ci], tB, mB[ci], dB[ci], aB[ci]);
            }
        }
        float oA[4], oB[4];
#pragma unroll
        for (int ci = 0; ci < 4; ci++) {
            oA[ci] = aA[ci] / (dA[ci] + 1e-16f) + xc[ci];
            oB[ci] = aB[ci] / (dB[ci] + 1e-16f) + xc[ci];
        }
        pack_f16(oA, g_af16, gw, lane);
        pack_f16(oB, g_af16b, gw, lane);
    }
}

// ================= host orchestration =================
extern "C" void kernel_launch(void* const* d_in, const int* in_sizes, int n_in,
                              void* d_out, int out_size) {
    const float* x = (const float*)d_in[0];
    const int*   ei = (const int*)d_in[1];
    const float* t_all = (const float*)d_in[2];
    const float* W1 = (const float*)d_in[3];
    const float* W2 = (const float*)d_in[4];
    const float* gamma = (const float*)d_in[5];
    const float* beta = (const float*)d_in[6];

    const int N = in_sizes[0] / DD;
    const int E = in_sizes[1] / 2;
    const int* src = ei;
    const int* dst = ei + E;
    float* out = (float*)d_out;

    cudaFuncSetAttribute(gemm1_p3, cudaFuncAttributeMaxDynamicSharedMemorySize, 4 * CHSZ4);
    cudaFuncSetAttribute(gemm1_p2, cudaFuncAttributeMaxDynamicSharedMemorySize, 4 * CHSZ3);
    cudaFuncSetAttribute(gemm2_p3, cudaFuncAttributeMaxDynamicSharedMemorySize, 2 * CHSZ4);
    cudaFuncSetAttribute(gemm2_p2, cudaFuncAttributeMaxDynamicSharedMemorySize, 2 * CHSZ3);

    float* hA; cudaGetSymbolAddress((void**)&hA, g_hA);
    float* hB; cudaGetSymbolAddress((void**)&hB, g_hB);
    float* h1; cudaGetSymbolAddress((void**)&h1, g_h1);
    float* h1b; cudaGetSymbolAddress((void**)&h1b, g_h1b);
    float* sS; cudaGetSymbolAddress((void**)&sS, g_statS);
    float* sQ; cudaGetSymbolAddress((void**)&sQ, g_statQ);
    __half *ahh, *ahl, *af, *afb, *w1h, *w1l, *w2h, *w2l;
    cudaGetSymbolAddress((void**)&ahh, g_ahh);
    cudaGetSymbolAddress((void**)&ahl, g_ahl);
    cudaGetSymbolAddress((void**)&af, g_af16);
    cudaGetSymbolAddress((void**)&afb, g_af16b);
    cudaGetSymbolAddress((void**)&w1h, g_w1h);
    cudaGetSymbolAddress((void**)&w1l, g_w1l);
    cudaGetSymbolAddress((void**)&w2h, g_w2h);
    cudaGetSymbolAddress((void**)&w2l, g_w2l);

    const int mtiles = (N + 127) / 128;

    pack_w_kernel<<<1024, 256>>>(W1, W2, N);
    hist_kernel<<<(E + 255) / 256, 256>>>(dst, E, N);
    blockscan_kernel<<<NB, 256>>>(N);
    scanbsum_kernel<<<1, 512>>>(NB);
    rowptr_kernel<<<NB, 256>>>(N, E);
    scatter_kernel<<<(E + 255) / 256, 256>>>(src, dst, E, N);

    const int AG = (N * 32 + 255) / 256;

    // ---- layer 0 (3-pass everywhere) ----
    aggr_kernel<<<AG, 256>>>(x, t_all, 0, N);
    gemm1_p3<<<dim3(2, mtiles), 256, 4 * CHSZ4>>>(
        ahh, ahl, w1h + 0 * 32768, w1l + 0 * 32768, h1, sS + 0 * DD2, sQ + 0 * DD2, N);
    gemm2_p3<<<dim3(1, mtiles), 256, 2 * CHSZ4>>>(
        h1, w2h + 0 * 32768, w2l + 0 * 32768, hA, gamma, beta, 0, N);
    // ---- layer 1 (3-pass) ----
    aggr_kernel<<<AG, 256>>>(hA, t_all, 1, N);
    gemm1_p3<<<dim3(2, mtiles), 256, 4 * CHSZ4>>>(
        ahh, ahl, w1h + 1 * 32768, w1l + 1 * 32768, h1, sS + 1 * DD2, sQ + 1 * DD2, N);
    gemm2_p3<<<dim3(1, mtiles), 256, 2 * CHSZ4>>>(
        h1, w2h + 1 * 32768, w2l + 1 * 32768, hB, gamma, beta, 1, N);
    // ---- layers 2 & 3 (mu, logstd): 2-pass, z-batched ----
    aggr_dual_kernel<<<AG, 256>>>(hB, t_all, N);
    gemm1_p2<<<dim3(2, mtiles, 2), 256, 4 * CHSZ3>>>(
        af, afb, w1h + 2 * 32768, w1l + 2 * 32768, h1, h1b,
        sS + 2 * DD2, sQ + 2 * DD2, N);
    gemm2_p2<<<dim3(1, mtiles, 2), 256, 2 * CHSZ3>>>(
        h1, h1b, w2h + 2 * 32768, w2l + 2 * 32768, out, out + (size_t)N * DD,
        gamma, beta, 2, N);
}

// round 15
// speedup vs baseline: 1.2168x; 1.1496x over previous
#include <cuda_runtime.h>
#include <cuda_fp16.h>
#include <math.h>
#include <stdint.h>

#define NN 100000
#define NPAD 100128
#define DD 128
#define DD2 256
#define EE 800000
#define NB ((NN + 255) / 256)
#define STRD 48          // k16 chunk: 16 elems*2B = 32B + 16B pad -> LDSM conflict-free
#define SEG 6144         // 128*48
#define CHSZ3 18432      // 3 segments (A, B_hi, B_lo)
#define CHSZ4 24576      // 4 segments (A_hi, A_lo, B_hi, B_lo)

// ================= scratch =================
__device__ float g_hA[NN * DD];
__device__ float g_hB[NN * DD];
__device__ float g_h1[NN * DD2];
__device__ float g_h1b[NN * DD2];
__device__ float g_statS[4 * DD2];
__device__ float g_statQ[4 * DD2];
__device__ int   g_dualsame;                           // t_all[2]==t_all[3] flag
__device__ __align__(256) __half g_ahh[NPAD * DD];   // aggr out hi (layers 0,1)
__device__ __align__(256) __half g_ahl[NPAD * DD];   // aggr out lo
__device__ __align__(256) __half g_af16[NPAD * DD];  // aggr out single fp16 (layer 2)
__device__ __align__(256) __half g_af16b[NPAD * DD]; // (layer 3; unused if dualsame)
__device__ __align__(256) __half g_w1h[4 * 256 * 128];  // [l][n][k] fp16 hi
__device__ __align__(256) __half g_w1l[4 * 256 * 128];
__device__ __align__(256) __half g_w2h[4 * 128 * 256];  // [l][n][k] fp16 hi
__device__ __align__(256) __half g_w2l[4 * 128 * 256];
__device__ int g_deg[NN];
__device__ int g_scan[NN];
__device__ int g_bsum[512];
__device__ int g_boff[512];
__device__ int g_rowptr[NN + 1];
__device__ int g_cursor[NN];
__device__ int g_csr_src[EE];

// ================= small helpers =================
__device__ __forceinline__ uint32_t smem_u32(const void* p) {
    uint32_t a;
    asm("{ .reg .u64 t; cvta.to.shared.u64 t, %1; cvt.u32.u64 %0, t; }"
        : "=r"(a) : "l"(p));
    return a;
}
#define CP_ASYNC16(sa, ga) \
    asm volatile("cp.async.cg.shared.global [%0], [%1], 16;" :: "r"(sa), "l"(ga))
#define CP_COMMIT() asm volatile("cp.async.commit_group;")
#define CP_WAIT0() asm volatile("cp.async.wait_group 0;")
#define CP_WAIT1() asm volatile("cp.async.wait_group 1;")
#define CP_WAIT2() asm volatile("cp.async.wait_group 2;")

__device__ __forceinline__ void ldsm_x4(uint32_t* r, uint32_t addr) {
    asm volatile("ldmatrix.sync.aligned.m8n8.x4.shared.b16 {%0,%1,%2,%3}, [%4];"
                 : "=r"(r[0]), "=r"(r[1]), "=r"(r[2]), "=r"(r[3]) : "r"(addr));
}
__device__ __forceinline__ void mma_f16(float* c, const uint32_t* a, const uint32_t* b) {
    asm volatile(
        "mma.sync.aligned.m16n8k16.row.col.f32.f16.f16.f32 "
        "{%0,%1,%2,%3}, {%4,%5,%6,%7}, {%8,%9}, {%0,%1,%2,%3};"
        : "+f"(c[0]), "+f"(c[1]), "+f"(c[2]), "+f"(c[3])
        : "r"(a[0]), "r"(a[1]), "r"(a[2]), "r"(a[3]), "r"(b[0]), "r"(b[1]));
}

// ---- 2-pass chunk: segs [A, Bh, Bl]; C += A*Bh + A*Bl. 10 LDSM + 32 MMA ----
__device__ __forceinline__ void mma_chunk2(uint32_t buf, int wm, int wn, int g, int r,
                                           float c[2][8][4]) {
    uint32_t a[2][4], bf[16];
    uint32_t acol = (uint32_t)(g >> 1) * 16;
    uint32_t bcol = (uint32_t)(g & 1) * 16;
#pragma unroll
    for (int mt = 0; mt < 2; mt++) {
        uint32_t arow = (uint32_t)(wm + mt * 16 + (g & 1) * 8 + r);
        ldsm_x4(a[mt], buf + arow * STRD + acol);
    }
#pragma unroll
    for (int nb = 0; nb < 4; nb++) {
        uint32_t brow = (uint32_t)(wn + nb * 16 + (g >> 1) * 8 + r);
        ldsm_x4(&bf[nb * 4], buf + SEG + brow * STRD + bcol);
    }
#pragma unroll
    for (int mt = 0; mt < 2; mt++)
#pragma unroll
        for (int nt = 0; nt < 8; nt++) mma_f16(c[mt][nt], a[mt], &bf[nt * 2]);
#pragma unroll
    for (int nb = 0; nb < 4; nb++) {
        uint32_t brow = (uint32_t)(wn + nb * 16 + (g >> 1) * 8 + r);
        ldsm_x4(&bf[nb * 4], buf + 2 * SEG + brow * STRD + bcol);
    }
#pragma unroll
    for (int mt = 0; mt < 2; mt++)
#pragma unroll
        for (int nt = 0; nt < 8; nt++) mma_f16(c[mt][nt], a[mt], &bf[nt * 2]);
}

// ---- 3-pass chunk: segs [Ah, Al, Bh, Bl]; C += Ah*Bh + Al*Bh + Ah*Bl ----
__device__ __forceinline__ void mma_chunk3(uint32_t buf, int wm, int wn, int g, int r,
                                           float c[2][8][4]) {
    uint32_t ah[2][4], al[2][4], bf[16];
    uint32_t acol = (uint32_t)(g >> 1) * 16;
    uint32_t bcol = (uint32_t)(g & 1) * 16;
#pragma unroll
    for (int mt = 0; mt < 2; mt++) {
        uint32_t arow = (uint32_t)(wm + mt * 16 + (g & 1) * 8 + r);
        ldsm_x4(ah[mt], buf + arow * STRD + acol);
        ldsm_x4(al[mt], buf + SEG + arow * STRD + acol);
    }
#pragma unroll
    for (int nb = 0; nb < 4; nb++) {
        uint32_t brow = (uint32_t)(wn + nb * 16 + (g >> 1) * 8 + r);
        ldsm_x4(&bf[nb * 4], buf + 2 * SEG + brow * STRD + bcol);
    }
#pragma unroll
    for (int mt = 0; mt < 2; mt++)
#pragma unroll
        for (int nt = 0; nt < 8; nt++) mma_f16(c[mt][nt], ah[mt], &bf[nt * 2]);
#pragma unroll
    for (int mt = 0; mt < 2; mt++)
#pragma unroll
        for (int nt = 0; nt < 8; nt++) mma_f16(c[mt][nt], al[mt], &bf[nt * 2]);
#pragma unroll
    for (int nb = 0; nb < 4; nb++) {
        uint32_t brow = (uint32_t)(wn + nb * 16 + (g >> 1) * 8 + r);
        ldsm_x4(&bf[nb * 4], buf + 3 * SEG + brow * STRD + bcol);
    }
#pragma unroll
    for (int mt = 0; mt < 2; mt++)
#pragma unroll
        for (int nt = 0; nt < 8; nt++) mma_f16(c[mt][nt], ah[mt], &bf[nt * 2]);
}

// cp.async one segment: 128 rows x 32B/row
template <typename T>
__device__ __forceinline__ void seg_cp(uint32_t sm, const T* gsrc,
                                       int row0g, int ldk, int k0, int tid) {
    int m = tid >> 1, sub = tid & 1;
    uint32_t sa = sm + m * STRD + sub * 16;
    const void* ga = gsrc + (size_t)(row0g + m) * ldk + k0 + sub * 8;
    CP_ASYNC16(sa, ga);
}

// ---- shared epilogue pieces ----
__device__ __forceinline__ void store_c(float c[2][8][4], float* C, int row0, int col0,
                                        int NOUT, int wm, int wn, int lane, int M,
                                        bool relu) {
#pragma unroll
    for (int mt = 0; mt < 2; mt++) {
        int rb = row0 + wm + mt * 16 + (lane >> 2);
#pragma unroll
        for (int nt = 0; nt < 8; nt++) {
            int cb = col0 + wn + nt * 8 + (lane & 3) * 2;
            float2 v0 = make_float2(c[mt][nt][0], c[mt][nt][1]);
            float2 v1 = make_float2(c[mt][nt][2], c[mt][nt][3]);
            if (relu) {
                v0.x = fmaxf(v0.x, 0.f); v0.y = fmaxf(v0.y, 0.f);
                v1.x = fmaxf(v1.x, 0.f); v1.y = fmaxf(v1.y, 0.f);
            }
            if (rb < M)     *(float2*)&C[(size_t)rb * NOUT + cb] = v0;
            if (rb + 8 < M) *(float2*)&C[(size_t)(rb + 8) * NOUT + cb] = v1;
        }
    }
}
__device__ __forceinline__ void bn_stats_epi(float c[2][8][4], float* statS, float* statQ,
                                             int col0, int wn, int lane) {
    float s16[16], q16[16];
#pragma unroll
    for (int nt = 0; nt < 8; nt++)
#pragma unroll
        for (int j = 0; j < 2; j++) {
            float a0 = c[0][nt][j], a1 = c[0][nt][j + 2];
            float a2 = c[1][nt][j], a3 = c[1][nt][j + 2];
            s16[nt * 2 + j] = a0 + a1 + a2 + a3;
            q16[nt * 2 + j] = a0 * a0 + a1 * a1 + a2 * a2 + a3 * a3;
        }
#pragma unroll
    for (int i = 0; i < 16; i++) {
#pragma unroll
        for (int off = 4; off < 32; off <<= 1) {
            s16[i] += __shfl_xor_sync(0xffffffffu, s16[i], off);
            q16[i] += __shfl_xor_sync(0xffffffffu, q16[i], off);
        }
    }
    if ((lane >> 2) == 0) {
#pragma unroll
        for (int nt = 0; nt < 8; nt++)
#pragma unroll
            for (int j = 0; j < 2; j++) {
                int col = col0 + wn + nt * 8 + (lane & 3) * 2 + j;
                atomicAdd(&statS[col], s16[nt * 2 + j]);
                atomicAdd(&statQ[col], q16[nt * 2 + j]);
            }
    }
}

// ===== GEMM1 3-pass (layers 0,1): A hi/lo fp16 x B hi/lo, fused BN stats =====
__global__ void __launch_bounds__(256, 2)
gemm1_p3(const __half* __restrict__ Ah, const __half* __restrict__ Al,
         const __half* __restrict__ Bh, const __half* __restrict__ Bl,
         float* __restrict__ C, float* __restrict__ statS, float* __restrict__ statQ,
         int M) {
    extern __shared__ __align__(128) char dsm[];
    const uint32_t base = smem_u32(dsm);
    constexpr int KTOT = 128, NOUT = 256, NC = 8;

    int tid = threadIdx.x;
    int wid = tid >> 5, lane = tid & 31;
    int wm = (wid & 3) * 32, wn = (wid >> 2) * 64;
    int row0 = blockIdx.y * 128, col0 = blockIdx.x * 128;
    int g = lane >> 3, r = lane & 7;

    float c[2][8][4];
#pragma unroll
    for (int i = 0; i < 2; i++)
#pragma unroll
        for (int j = 0; j < 8; j++)
#pragma unroll
            for (int q = 0; q < 4; q++) c[i][j][q] = 0.0f;

    auto stage = [&](int ch) {
        uint32_t b = base + (ch & 3) * CHSZ4;
        int k0 = ch * 16;
        seg_cp(b + 0 * SEG, Ah, row0, KTOT, k0, tid);
        seg_cp(b + 1 * SEG, Al, row0, KTOT, k0, tid);
        seg_cp(b + 2 * SEG, Bh, col0, KTOT, k0, tid);
        seg_cp(b + 3 * SEG, Bl, col0, KTOT, k0, tid);
        CP_COMMIT();
    };

    stage(0); stage(1); stage(2);

#pragma unroll 1
    for (int ch = 0; ch < NC - 3; ch++) {
        CP_WAIT2();
        __syncthreads();
        stage(ch + 3);
        mma_chunk3(base + (ch & 3) * CHSZ4, wm, wn, g, r, c);
    }
    CP_WAIT2(); __syncthreads();
    mma_chunk3(base + ((NC - 3) & 3) * CHSZ4, wm, wn, g, r, c);
    CP_WAIT1(); __syncthreads();
    mma_chunk3(base + ((NC - 2) & 3) * CHSZ4, wm, wn, g, r, c);
    CP_WAIT0(); __syncthreads();
    mma_chunk3(base + ((NC - 1) & 3) * CHSZ4, wm, wn, g, r, c);

    store_c(c, C, row0, col0, NOUT, wm, wn, lane, M, false);
    bn_stats_epi(c, statS, statQ, col0, wn, lane);
}

// ===== GEMM1 2-pass (layers 2,3 z-batched): single-fp16 A x B hi/lo =====
__global__ void __launch_bounds__(256, 2)
gemm1_p2(const __half* __restrict__ A0, const __half* __restrict__ A1,
         const __half* __restrict__ Bh_base, const __half* __restrict__ Bl_base,
         float* __restrict__ C0, float* __restrict__ C1,
         float* __restrict__ statS_base, float* __restrict__ statQ_base, int M) {
    extern __shared__ __align__(128) char dsm[];
    const uint32_t base = smem_u32(dsm);
    constexpr int KTOT = 128, NOUT = 256, NC = 8;

    int z = blockIdx.z;
    const __half* Af = (z && !g_dualsame) ? A1 : A0;   // dedup when t2==t3
    const __half* Bh = Bh_base + (size_t)z * KTOT * NOUT;
    const __half* Bl = Bl_base + (size_t)z * KTOT * NOUT;
    float* C = z ? C1 : C0;

    int tid = threadIdx.x;
    int wid = tid >> 5, lane = tid & 31;
    int wm = (wid & 3) * 32, wn = (wid >> 2) * 64;
    int row0 = blockIdx.y * 128, col0 = blockIdx.x * 128;
    int g = lane >> 3, r = lane & 7;

    float c[2][8][4];
#pragma unroll
    for (int i = 0; i < 2; i++)
#pragma unroll
        for (int j = 0; j < 8; j++)
#pragma unroll
            for (int q = 0; q < 4; q++) c[i][j][q] = 0.0f;

    auto stage = [&](int ch) {
        uint32_t b = base + (ch & 3) * CHSZ3;
        int k0 = ch * 16;
        seg_cp(b + 0 * SEG, Af, row0, KTOT, k0, tid);
        seg_cp(b + 1 * SEG, Bh, col0, KTOT, k0, tid);
        seg_cp(b + 2 * SEG, Bl, col0, KTOT, k0, tid);
        CP_COMMIT();
    };

    stage(0); stage(1); stage(2);

#pragma unroll 1
    for (int ch = 0; ch < NC - 3; ch++) {
        CP_WAIT2();
        __syncthreads();
        stage(ch + 3);
        mma_chunk2(base + (ch & 3) * CHSZ3, wm, wn, g, r, c);
    }
    CP_WAIT2(); __syncthreads();
    mma_chunk2(base + ((NC - 3) & 3) * CHSZ3, wm, wn, g, r, c);
    CP_WAIT1(); __syncthreads();
    mma_chunk2(base + ((NC - 2) & 3) * CHSZ3, wm, wn, g, r, c);
    CP_WAIT0(); __syncthreads();
    mma_chunk2(base + ((NC - 1) & 3) * CHSZ3, wm, wn, g, r, c);

    store_c(c, C, row0, col0, NOUT, wm, wn, lane, M, false);
    bn_stats_epi(c, statS_base + z * DD2, statQ_base + z * DD2, col0, wn, lane);
}

// ===== GEMM2 3-pass (layers 0,1): fp32 A + fused-BN prolog -> fp16 hi/lo =====
__global__ void __launch_bounds__(256, 2)
gemm2_p3(const float* __restrict__ Af,
         const __half* __restrict__ Bh, const __half* __restrict__ Bl,
         float* __restrict__ C,
         const float* __restrict__ gamma, const float* __restrict__ beta,
         int l, int M) {
    extern __shared__ __align__(128) char dsm[];
    __shared__ float s_scale[DD2];
    __shared__ float s_shift[DD2];
    const uint32_t base = smem_u32(dsm);
    constexpr int KTOT = 256, NOUT = 128, NC = 16;

    int tid = threadIdx.x;
    int wid = tid >> 5, lane = tid & 31;
    int wm = (wid & 3) * 32, wn = (wid >> 2) * 64;
    int row0 = blockIdx.y * 128;
    int g = lane >> 3, r = lane & 7;

    {
        int cc = tid;
        float s = g_statS[l * DD2 + cc];
        float q = g_statQ[l * DD2 + cc];
        float mean = s / (float)M;
        float var = q / (float)M - mean * mean;
        float inv = rsqrtf(var + 1e-5f);
        float sc = inv * gamma[l * DD2 + cc];
        s_scale[cc] = sc;
        s_shift[cc] = beta[l * DD2 + cc] - mean * sc;
    }
    __syncthreads();

    float c[2][8][4];
#pragma unroll
    for (int i = 0; i < 2; i++)
#pragma unroll
        for (int j = 0; j < 8; j++)
#pragma unroll
            for (int q = 0; q < 4; q++) c[i][j][q] = 0.0f;

    int am = tid >> 1;
    int asub = tid & 1;
    float av[8];

    auto stageB = [&](int ch) {
        uint32_t b = base + (ch & 1) * CHSZ4;
        int k0 = ch * 16;
        seg_cp(b + 2 * SEG, Bh, 0, KTOT, k0, tid);
        seg_cp(b + 3 * SEG, Bl, 0, KTOT, k0, tid);
        CP_COMMIT();
    };
    auto ldgA = [&](int ch) {
        int row = row0 + am;
        int k0 = ch * 16 + asub * 8;
        if (row < M) {
            float4 u0 = *(const float4*)&Af[(size_t)row * KTOT + k0];
            float4 u1 = *(const float4*)&Af[(size_t)row * KTOT + k0 + 4];
            av[0]=u0.x; av[1]=u0.y; av[2]=u0.z; av[3]=u0.w;
            av[4]=u1.x; av[5]=u1.y; av[6]=u1.z; av[7]=u1.w;
        } else {
#pragma unroll
            for (int p = 0; p < 8; p++) av[p] = 0.f;
        }
    };
    auto stsA = [&](int ch) {
        uint32_t b = base + (ch & 1) * CHSZ4;
        int k0 = ch * 16 + asub * 8;
        uint32_t hp[4], lp[4];
#pragma unroll
        for (int p = 0; p < 4; p++) {
            float a0 = fmaxf(av[2*p]   * s_scale[k0 + 2*p]   + s_shift[k0 + 2*p],   0.f);
            float a1 = fmaxf(av[2*p+1] * s_scale[k0 + 2*p+1] + s_shift[k0 + 2*p+1], 0.f);
            __half2 hh = __floats2half2_rn(a0, a1);
            __half2 ll = __floats2half2_rn(a0 - __half2float(__low2half(hh)),
                                           a1 - __half2float(__high2half(hh)));
            hp[p] = *(uint32_t*)&hh;
            lp[p] = *(uint32_t*)&ll;
        }
        uint32_t off = (b - base) + am * STRD + asub * 16;
        *(uint4*)(dsm + off)       = make_uint4(hp[0], hp[1], hp[2], hp[3]);
        *(uint4*)(dsm + SEG + off) = make_uint4(lp[0], lp[1], lp[2], lp[3]);
    };

    stageB(0);
    ldgA(0);
    stsA(0);
    ldgA(1);
    CP_WAIT0();
    __syncthreads();

#pragma unroll 1
    for (int ch = 0; ch < NC; ch++) {
        bool hn = (ch + 1 < NC);
        if (hn) { stageB(ch + 1); stsA(ch + 1); }
        if (ch + 2 < NC) ldgA(ch + 2);
        mma_chunk3(base + (ch & 1) * CHSZ4, wm, wn, g, r, c);
        if (hn) CP_WAIT0();
        __syncthreads();
    }

    store_c(c, C, row0, 0, NOUT, wm, wn, lane, M, true);
}

// ===== GEMM2 2-pass (final mu/logstd, z-batched): single-fp16 A prolog =====
__global__ void __launch_bounds__(256, 2)
gemm2_p2(const float* __restrict__ A0, const float* __restrict__ A1,
         const __half* __restrict__ Bh_base, const __half* __restrict__ Bl_base,
         float* __restrict__ C0, float* __restrict__ C1,
         const float* __restrict__ gamma, const float* __restrict__ beta,
         int layer0, int M) {
    extern __shared__ __align__(128) char dsm[];
    __shared__ float s_scale[DD2];
    __shared__ float s_shift[DD2];
    const uint32_t base = smem_u32(dsm);
    constexpr int KTOT = 256, NOUT = 128, NC = 16;

    int z = blockIdx.z;
    int l = layer0 + z;
    const float* Af = z ? A1 : A0;
    const __half* Bh = Bh_base + (size_t)z * KTOT * NOUT;
    const __half* Bl = Bl_base + (size_t)z * KTOT * NOUT;
    float* C = z ? C1 : C0;

    int tid = threadIdx.x;
    int wid = tid >> 5, lane = tid & 31;
    int wm = (wid & 3) * 32, wn = (wid >> 2) * 64;
    int row0 = blockIdx.y * 128;
    int g = lane >> 3, r = lane & 7;

    {
        int cc = tid;
        float s = g_statS[l * DD2 + cc];
        float q = g_statQ[l * DD2 + cc];
        float mean = s / (float)M;
        float var = q / (float)M - mean * mean;
        float inv = rsqrtf(var + 1e-5f);
        float sc = inv * gamma[l * DD2 + cc];
        s_scale[cc] = sc;
        s_shift[cc] = beta[l * DD2 + cc] - mean * sc;
    }
    __syncthreads();

    float c[2][8][4];
#pragma unroll
    for (int i = 0; i < 2; i++)
#pragma unroll
        for (int j = 0; j < 8; j++)
#pragma unroll
            for (int q = 0; q < 4; q++) c[i][j][q] = 0.0f;

    int am = tid >> 1;
    int asub = tid & 1;
    float av[8];

    auto stageB = [&](int ch) {
        uint32_t b = base + (ch & 1) * CHSZ3;
        int k0 = ch * 16;
        seg_cp(b + 1 * SEG, Bh, 0, KTOT, k0, tid);
        seg_cp(b + 2 * SEG, Bl, 0, KTOT, k0, tid);
        CP_COMMIT();
    };
    auto ldgA = [&](int ch) {
        int row = row0 + am;
        int k0 = ch * 16 + asub * 8;
        if (row < M) {
            float4 u0 = *(const float4*)&Af[(size_t)row * KTOT + k0];
            float4 u1 = *(const float4*)&Af[(size_t)row * KTOT + k0 + 4];
            av[0]=u0.x; av[1]=u0.y; av[2]=u0.z; av[3]=u0.w;
            av[4]=u1.x; av[5]=u1.y; av[6]=u1.z; av[7]=u1.w;
        } else {
#pragma unroll
            for (int p = 0; p < 8; p++) av[p] = 0.f;
        }
    };
    auto stsA = [&](int ch) {
        uint32_t b = base + (ch & 1) * CHSZ3;
        int k0 = ch * 16 + asub * 8;
        uint32_t hp[4];
#pragma unroll
        for (int p = 0; p < 4; p++) {
            float a0 = fmaxf(av[2*p]   * s_scale[k0 + 2*p]   + s_shift[k0 + 2*p],   0.f);
            float a1 = fmaxf(av[2*p+1] * s_scale[k0 + 2*p+1] + s_shift[k0 + 2*p+1], 0.f);
            __half2 hh = __floats2half2_rn(a0, a1);
            hp[p] = *(uint32_t*)&hh;
        }
        uint32_t off = (b - base) + am * STRD + asub * 16;
        *(uint4*)(dsm + off) = make_uint4(hp[0], hp[1], hp[2], hp[3]);
    };

    stageB(0);
    ldgA(0);
    stsA(0);
    ldgA(1);
    CP_WAIT0();
    __syncthreads();

#pragma unroll 1
    for (int ch = 0; ch < NC; ch++) {
        bool hn = (ch + 1 < NC);
        if (hn) { stageB(ch + 1); stsA(ch + 1); }
        if (ch + 2 < NC) ldgA(ch + 2);
        mma_chunk2(base + (ch & 1) * CHSZ3, wm, wn, g, r, c);
        if (hn) CP_WAIT0();
        __syncthreads();
    }

    store_c(c, C, row0, 0, NOUT, wm, wn, lane, M, false);
}

// ===== weight pack (W1, W2 fp16 hi/lo) + zero stats/deg =====
__global__ void pack_w_kernel(const float* __restrict__ W1, const float* __restrict__ W2,
                              int N) {
    int idx = blockIdx.x * blockDim.x + threadIdx.x;
    if (idx < 131072) {
        int l = idx >> 15, rr = idx & 32767;
        int k = rr >> 8, n = rr & 255;
        float v = W1[(size_t)l * 32768 + rr];
        __half h = __float2half_rn(v);
        __half lo = __float2half_rn(v - __half2float(h));
        int o = l * 32768 + n * 128 + k;
        g_w1h[o] = h; g_w1l[o] = lo;
    } else if (idx < 262144) {
        int j = idx - 131072;
        int l = j >> 15, rr = j & 32767;
        int k = rr >> 7, n = rr & 127;
        float v = W2[(size_t)l * 32768 + rr];
        __half h = __float2half_rn(v);
        __half lo = __float2half_rn(v - __half2float(h));
        int o = l * 32768 + n * 256 + k;
        g_w2h[o] = h; g_w2l[o] = lo;
    }
    if (idx < 1024) { g_statS[idx] = 0.f; g_statQ[idx] = 0.f; }
    if (idx < N) g_deg[idx] = 0;
}

// ================= CSR build =================
__global__ void hist_kernel(const int* __restrict__ dst, int E, int N) {
    int e = blockIdx.x * blockDim.x + threadIdx.x;
    if (e >= E) return;
    int d = dst[e];
    if ((unsigned)d < (unsigned)N) atomicAdd(&g_deg[d], 1);
}
__global__ void blockscan_kernel(int N) {
    __shared__ int sm[256];
    int i = blockIdx.x * 256 + threadIdx.x;
    int v = (i < N) ? g_deg[i] : 0;
    sm[threadIdx.x] = v;
    __syncthreads();
#pragma unroll
    for (int off = 1; off < 256; off <<= 1) {
        int t = (threadIdx.x >= off) ? sm[threadIdx.x - off] : 0;
        __syncthreads();
        sm[threadIdx.x] += t;
        __syncthreads();
    }
    if (i < N) g_scan[i] = sm[threadIdx.x];
    if (threadIdx.x == 255) g_bsum[blockIdx.x] = sm[255];
}
__global__ void scanbsum_kernel(int nb) {
    __shared__ int sm[512];
    int tid = threadIdx.x;
    int v = (tid < nb) ? g_bsum[tid] : 0;
    sm[tid] = v;
    __syncthreads();
#pragma unroll
    for (int off = 1; off < 512; off <<= 1) {
        int t = (tid >= off) ? sm[tid - off] : 0;
        __syncthreads();
        sm[tid] += t;
        __syncthreads();
    }
    if (tid < nb) g_boff[tid] = sm[tid] - v;
}
__global__ void rowptr_kernel(int N, int E) {
    int i = blockIdx.x * 256 + threadIdx.x;
    if (i < N) {
        int rp = g_scan[i] - g_deg[i] + g_boff[blockIdx.x];
        g_rowptr[i] = rp;
        g_cursor[i] = rp;
    }
    if (i == 0) g_rowptr[N] = E;
}
__global__ void scatter_kernel(const int* __restrict__ src,
                               const int* __restrict__ dst, int E, int N) {
    int e = blockIdx.x * blockDim.x + threadIdx.x;
    if (e >= E) return;
    int d = dst[e];
    int s = src[e];
    if ((unsigned)d >= (unsigned)N || (unsigned)s >= (unsigned)N) return;
    int pos = atomicAdd(&g_cursor[d], 1);
    g_csr_src[pos] = s;
}

// ======== aggregation: no-max softmax (logits = relu(x)*t, bounded << 88 so
// exp cannot overflow; epsilon perturbation vs reference is ~1e-16 relative) ====
__device__ __forceinline__ void supd(float v, float t, float& den, float& acc) {
    float msg = fmaxf(v, 0.0f) + 1e-7f;
    float w = __expf(msg * t);
    den += w;
    acc += w * msg;
}
__device__ __forceinline__ void pack_hl(const float* o, __half* H, __half* L,
                                        int gw, int lane) {
    __half2 h0 = __floats2half2_rn(o[0], o[1]);
    __half2 h1 = __floats2half2_rn(o[2], o[3]);
    __half2 l0 = __floats2half2_rn(o[0] - __low2float(h0), o[1] - __high2float(h0));
    __half2 l1 = __floats2half2_rn(o[2] - __low2float(h1), o[3] - __high2float(h1));
    uint2 uh, ul;
    uh.x = *(uint32_t*)&h0; uh.y = *(uint32_t*)&h1;
    ul.x = *(uint32_t*)&l0; ul.y = *(uint32_t*)&l1;
    ((uint2*)H)[gw * 32 + lane] = uh;
    ((uint2*)L)[gw * 32 + lane] = ul;
}
__device__ __forceinline__ void pack_f16(const float* o, __half* H, int gw, int lane) {
    __half2 p0 = __floats2half2_rn(o[0], o[1]);
    __half2 p1 = __floats2half2_rn(o[2], o[3]);
    uint2 u;
    u.x = *(uint32_t*)&p0;
    u.y = *(uint32_t*)&p1;
    ((uint2*)H)[gw * 32 + lane] = u;
}

__global__ void aggr_kernel(const float* __restrict__ x,
                            const float* __restrict__ t_all, int layer, int N) {
    int gw = (blockIdx.x * 256 + threadIdx.x) >> 5;
    int lane = threadIdx.x & 31;
    if (gw >= N) return;
    int beg = g_rowptr[gw], end = g_rowptr[gw + 1];
    float t = __ldg(&t_all[layer]);
    const float4* x4 = (const float4*)x;
    float d[4] = {0, 0, 0, 0}, a[4] = {0, 0, 0, 0};
    int sj = (beg < end) ? g_csr_src[beg] : 0;
    for (int j = beg; j < end; j++) {
        int s = sj;
        if (j + 1 < end) sj = g_csr_src[j + 1];
        float4 v = __ldg(&x4[s * 32 + lane]);
        supd(v.x, t, d[0], a[0]);
        supd(v.y, t, d[1], a[1]);
        supd(v.z, t, d[2], a[2]);
        supd(v.w, t, d[3], a[3]);
    }
    float4 xv = __ldg(&x4[gw * 32 + lane]);
    float xc[4] = {xv.x, xv.y, xv.z, xv.w};
    float o[4];
#pragma unroll
    for (int ci = 0; ci < 4; ci++) o[ci] = a[ci] / (d[ci] + 1e-16f) + xc[ci];
    pack_hl(o, g_ahh, g_ahl, gw, lane);
}

__global__ void aggr_dual_kernel(const float* __restrict__ x,
                                 const float* __restrict__ t_all, int N) {
    int gw = (blockIdx.x * 256 + threadIdx.x) >> 5;
    int lane = threadIdx.x & 31;
    if (gw >= N) return;
    int beg = g_rowptr[gw], end = g_rowptr[gw + 1];
    float tA = __ldg(&t_all[2]);
    float tB = __ldg(&t_all[3]);
    const float4* x4 = (const float4*)x;
    float4 xv = __ldg(&x4[gw * 32 + lane]);
    float xc[4] = {xv.x, xv.y, xv.z, xv.w};

    if (tA == tB) {
        if (gw == 0 && lane == 0) g_dualsame = 1;
        float d[4] = {0, 0, 0, 0}, a[4] = {0, 0, 0, 0};
        int sj = (beg < end) ? g_csr_src[beg] : 0;
        for (int j = beg; j < end; j++) {
            int s = sj;
            if (j + 1 < end) sj = g_csr_src[j + 1];
            float4 v = __ldg(&x4[s * 32 + lane]);
            supd(v.x, tA, d[0], a[0]);
            supd(v.y, tA, d[1], a[1]);
            supd(v.z, tA, d[2], a[2]);
            supd(v.w, tA, d[3], a[3]);
        }
        float o[4];
#pragma unroll
        for (int ci = 0; ci < 4; ci++) o[ci] = a[ci] / (d[ci] + 1e-16f) + xc[ci];
        pack_f16(o, g_af16, gw, lane);   // single copy; consumers dedup via flag
    } else {
        if (gw == 0 && lane == 0) g_dualsame = 0;
        float dA[4] = {0, 0, 0, 0}, aA[4] = {0, 0, 0, 0};
        float dB[4] = {0, 0, 0, 0}, aB[4] = {0, 0, 0, 0};
        int sj = (beg < end) ? g_csr_src[beg] : 0;
        for (int j = beg; j < end; j++) {
            int s = sj;
            if (j + 1 < end) sj = g_csr_src[j + 1];
            float4 v = __ldg(&x4[s * 32 + lane]);
            float vv[4] = {v.x, v.y, v.z, v.w};
#pragma unroll
            for (int ci = 0; ci < 4; ci++) {
                supd(vv[ci], tA, dA[ci], aA[ci]);
                supd(vv[ci], tB, dB[ci], aB[ci]);
            }
        }
        float oA[4], oB[4];
#pragma unroll
        for (int ci = 0; ci < 4; ci++) {
            oA[ci] = aA[ci] / (dA[ci] + 1e-16f) + xc[ci];
            oB[ci] = aB[ci] / (dB[ci] + 1e-16f) + xc[ci];
        }
        pack_f16(oA, g_af16, gw, lane);
        pack_f16(oB, g_af16b, gw, lane);
    }
}

// ================= host orchestration =================
extern "C" void kernel_launch(void* const* d_in, const int* in_sizes, int n_in,
                              void* d_out, int out_size) {
    const float* x = (const float*)d_in[0];
    const int*   ei = (const int*)d_in[1];
    const float* t_all = (const float*)d_in[2];
    const float* W1 = (const float*)d_in[3];
    const float* W2 = (const float*)d_in[4];
    const float* gamma = (const float*)d_in[5];
    const float* beta = (const float*)d_in[6];

    const int N = in_sizes[0] / DD;
    const int E = in_sizes[1] / 2;
    const int* src = ei;
    const int* dst = ei + E;
    float* out = (float*)d_out;

    cudaFuncSetAttribute(gemm1_p3, cudaFuncAttributeMaxDynamicSharedMemorySize, 4 * CHSZ4);
    cudaFuncSetAttribute(gemm1_p2, cudaFuncAttributeMaxDynamicSharedMemorySize, 4 * CHSZ3);
    cudaFuncSetAttribute(gemm2_p3, cudaFuncAttributeMaxDynamicSharedMemorySize, 2 * CHSZ4);
    cudaFuncSetAttribute(gemm2_p2, cudaFuncAttributeMaxDynamicSharedMemorySize, 2 * CHSZ3);

    float* hA; cudaGetSymbolAddress((void**)&hA, g_hA);
    float* hB; cudaGetSymbolAddress((void**)&hB, g_hB);
    float* h1; cudaGetSymbolAddress((void**)&h1, g_h1);
    float* h1b; cudaGetSymbolAddress((void**)&h1b, g_h1b);
    float* sS; cudaGetSymbolAddress((void**)&sS, g_statS);
    float* sQ; cudaGetSymbolAddress((void**)&sQ, g_statQ);
    __half *ahh, *ahl, *af, *afb, *w1h, *w1l, *w2h, *w2l;
    cudaGetSymbolAddress((void**)&ahh, g_ahh);
    cudaGetSymbolAddress((void**)&ahl, g_ahl);
    cudaGetSymbolAddress((void**)&af, g_af16);
    cudaGetSymbolAddress((void**)&afb, g_af16b);
    cudaGetSymbolAddress((void**)&w1h, g_w1h);
    cudaGetSymbolAddress((void**)&w1l, g_w1l);
    cudaGetSymbolAddress((void**)&w2h, g_w2h);
    cudaGetSymbolAddress((void**)&w2l, g_w2l);

    const int mtiles = (N + 127) / 128;

    pack_w_kernel<<<1024, 256>>>(W1, W2, N);
    hist_kernel<<<(E + 255) / 256, 256>>>(dst, E, N);
    blockscan_kernel<<<NB, 256>>>(N);
    scanbsum_kernel<<<1, 512>>>(NB);
    rowptr_kernel<<<NB, 256>>>(N, E);
    scatter_kernel<<<(E + 255) / 256, 256>>>(src, dst, E, N);

    const int AG = (N * 32 + 255) / 256;

    // ---- layer 0 (3-pass everywhere) ----
    aggr_kernel<<<AG, 256>>>(x, t_all, 0, N);
    gemm1_p3<<<dim3(2, mtiles), 256, 4 * CHSZ4>>>(
        ahh, ahl, w1h + 0 * 32768, w1l + 0 * 32768, h1, sS + 0 * DD2, sQ + 0 * DD2, N);
    gemm2_p3<<<dim3(1, mtiles), 256, 2 * CHSZ4>>>(
        h1, w2h + 0 * 32768, w2l + 0 * 32768, hA, gamma, beta, 0, N);
    // ---- layer 1 (3-pass) ----
    aggr_kernel<<<AG, 256>>>(hA, t_all, 1, N);
    gemm1_p3<<<dim3(2, mtiles), 256, 4 * CHSZ4>>>(
        ahh, ahl, w1h + 1 * 32768, w1l + 1 * 32768, h1, sS + 1 * DD2, sQ + 1 * DD2, N);
    gemm2_p3<<<dim3(1, mtiles), 256, 2 * CHSZ4>>>(
        h1, w2h + 1 * 32768, w2l + 1 * 32768, hB, gamma, beta, 1, N);
    // ---- layers 2 & 3 (mu, logstd): 2-pass, z-batched ----
    aggr_dual_kernel<<<AG, 256>>>(hB, t_all, N);
    gemm1_p2<<<dim3(2, mtiles, 2), 256, 4 * CHSZ3>>>(
        af, afb, w1h + 2 * 32768, w1l + 2 * 32768, h1, h1b,
        sS + 2 * DD2, sQ + 2 * DD2, N);
    gemm2_p2<<<dim3(1, mtiles, 2), 256, 2 * CHSZ3>>>(
        h1, h1b, w2h + 2 * 32768, w2l + 2 * 32768, out, out + (size_t)N * DD,
        gamma, beta, 2, N);
}

// round 16
// speedup vs baseline: 1.2425x; 1.0212x over previous
#include <cuda_runtime.h>
#include <cuda_fp16.h>
#include <math.h>
#include <stdint.h>

#define NN 100000
#define NPAD 100128
#define DD 128
#define DD2 256
#define EE 800000
#define NB ((NN + 255) / 256)
#define STRD 48          // k16 chunk: 16 elems*2B = 32B + 16B pad -> LDSM conflict-free
#define SEG 6144         // 128*48
#define CHSZ3 18432      // 3 segments (A, B_hi, B_lo)
#define CHSZ4 24576      // 4 segments (A_hi, A_lo, B_hi, B_lo)

// ================= scratch =================
__device__ float g_hA[NN * DD];
__device__ float g_hB[NN * DD];
__device__ float g_h1[NN * DD2];
__device__ float g_h1b[NN * DD2];
__device__ float g_statS[4 * DD2];
__device__ float g_statQ[4 * DD2];
__device__ int   g_dualsame;                           // t_all[2]==t_all[3] flag
__device__ __align__(256) __half g_ahh[NPAD * DD];   // aggr out hi (layer 0)
__device__ __align__(256) __half g_ahl[NPAD * DD];   // aggr out lo
__device__ __align__(256) __half g_af16[NPAD * DD];  // aggr out single fp16 (layers 1,2)
__device__ __align__(256) __half g_af16b[NPAD * DD]; // (layer 3; unused if dualsame)
__device__ __align__(256) __half g_w1h[4 * 256 * 128];  // [l][n][k] fp16 hi
__device__ __align__(256) __half g_w1l[4 * 256 * 128];
__device__ __align__(256) __half g_w2h[4 * 128 * 256];  // [l][n][k] fp16 hi
__device__ __align__(256) __half g_w2l[4 * 128 * 256];
__device__ int g_deg[NN];
__device__ int g_scan[NN];
__device__ int g_bsum[512];
__device__ int g_boff[512];
__device__ int g_rowptr[NN + 1];
__device__ int g_cursor[NN];
__device__ int g_csr_src[EE];

// ================= small helpers =================
__device__ __forceinline__ uint32_t smem_u32(const void* p) {
    uint32_t a;
    asm("{ .reg .u64 t; cvta.to.shared.u64 t, %1; cvt.u32.u64 %0, t; }"
        : "=r"(a) : "l"(p));
    return a;
}
#define CP_ASYNC16(sa, ga) \
    asm volatile("cp.async.cg.shared.global [%0], [%1], 16;" :: "r"(sa), "l"(ga))
#define CP_COMMIT() asm volatile("cp.async.commit_group;")
#define CP_WAIT0() asm volatile("cp.async.wait_group 0;")
#define CP_WAIT1() asm volatile("cp.async.wait_group 1;")
#define CP_WAIT2() asm volatile("cp.async.wait_group 2;")

__device__ __forceinline__ void ldsm_x4(uint32_t* r, uint32_t addr) {
    asm volatile("ldmatrix.sync.aligned.m8n8.x4.shared.b16 {%0,%1,%2,%3}, [%4];"
                 : "=r"(r[0]), "=r"(r[1]), "=r"(r[2]), "=r"(r[3]) : "r"(addr));
}
__device__ __forceinline__ void mma_f16(float* c, const uint32_t* a, const uint32_t* b) {
    asm volatile(
        "mma.sync.aligned.m16n8k16.row.col.f32.f16.f16.f32 "
        "{%0,%1,%2,%3}, {%4,%5,%6,%7}, {%8,%9}, {%0,%1,%2,%3};"
        : "+f"(c[0]), "+f"(c[1]), "+f"(c[2]), "+f"(c[3])
        : "r"(a[0]), "r"(a[1]), "r"(a[2]), "r"(a[3]), "r"(b[0]), "r"(b[1]));
}

// ---- 2-pass chunk: segs [A, Bh, Bl]; C += A*Bh + A*Bl. 10 LDSM + 32 MMA ----
__device__ __forceinline__ void mma_chunk2(uint32_t buf, int wm, int wn, int g, int r,
                                           float c[2][8][4]) {
    uint32_t a[2][4], bf[16];
    uint32_t acol = (uint32_t)(g >> 1) * 16;
    uint32_t bcol = (uint32_t)(g & 1) * 16;
#pragma unroll
    for (int mt = 0; mt < 2; mt++) {
        uint32_t arow = (uint32_t)(wm + mt * 16 + (g & 1) * 8 + r);
        ldsm_x4(a[mt], buf + arow * STRD + acol);
    }
#pragma unroll
    for (int nb = 0; nb < 4; nb++) {
        uint32_t brow = (uint32_t)(wn + nb * 16 + (g >> 1) * 8 + r);
        ldsm_x4(&bf[nb * 4], buf + SEG + brow * STRD + bcol);
    }
#pragma unroll
    for (int mt = 0; mt < 2; mt++)
#pragma unroll
        for (int nt = 0; nt < 8; nt++) mma_f16(c[mt][nt], a[mt], &bf[nt * 2]);
#pragma unroll
    for (int nb = 0; nb < 4; nb++) {
        uint32_t brow = (uint32_t)(wn + nb * 16 + (g >> 1) * 8 + r);
        ldsm_x4(&bf[nb * 4], buf + 2 * SEG + brow * STRD + bcol);
    }
#pragma unroll
    for (int mt = 0; mt < 2; mt++)
#pragma unroll
        for (int nt = 0; nt < 8; nt++) mma_f16(c[mt][nt], a[mt], &bf[nt * 2]);
}

// ---- 3-pass chunk: segs [Ah, Al, Bh, Bl]; C += Ah*Bh + Al*Bh + Ah*Bl ----
__device__ __forceinline__ void mma_chunk3(uint32_t buf, int wm, int wn, int g, int r,
                                           float c[2][8][4]) {
    uint32_t ah[2][4], al[2][4], bf[16];
    uint32_t acol = (uint32_t)(g >> 1) * 16;
    uint32_t bcol = (uint32_t)(g & 1) * 16;
#pragma unroll
    for (int mt = 0; mt < 2; mt++) {
        uint32_t arow = (uint32_t)(wm + mt * 16 + (g & 1) * 8 + r);
        ldsm_x4(ah[mt], buf + arow * STRD + acol);
        ldsm_x4(al[mt], buf + SEG + arow * STRD + acol);
    }
#pragma unroll
    for (int nb = 0; nb < 4; nb++) {
        uint32_t brow = (uint32_t)(wn + nb * 16 + (g >> 1) * 8 + r);
        ldsm_x4(&bf[nb * 4], buf + 2 * SEG + brow * STRD + bcol);
    }
#pragma unroll
    for (int mt = 0; mt < 2; mt++)
#pragma unroll
        for (int nt = 0; nt < 8; nt++) mma_f16(c[mt][nt], ah[mt], &bf[nt * 2]);
#pragma unroll
    for (int mt = 0; mt < 2; mt++)
#pragma unroll
        for (int nt = 0; nt < 8; nt++) mma_f16(c[mt][nt], al[mt], &bf[nt * 2]);
#pragma unroll
    for (int nb = 0; nb < 4; nb++) {
        uint32_t brow = (uint32_t)(wn + nb * 16 + (g >> 1) * 8 + r);
        ldsm_x4(&bf[nb * 4], buf + 3 * SEG + brow * STRD + bcol);
    }
#pragma unroll
    for (int mt = 0; mt < 2; mt++)
#pragma unroll
        for (int nt = 0; nt < 8; nt++) mma_f16(c[mt][nt], ah[mt], &bf[nt * 2]);
}

// cp.async one segment: 128 rows x 32B/row
template <typename T>
__device__ __forceinline__ void seg_cp(uint32_t sm, const T* gsrc,
                                       int row0g, int ldk, int k0, int tid) {
    int m = tid >> 1, sub = tid & 1;
    uint32_t sa = sm + m * STRD + sub * 16;
    const void* ga = gsrc + (size_t)(row0g + m) * ldk + k0 + sub * 8;
    CP_ASYNC16(sa, ga);
}

// ---- shared epilogue pieces ----
__device__ __forceinline__ void store_c(float c[2][8][4], float* C, int row0, int col0,
                                        int NOUT, int wm, int wn, int lane, int M,
                                        bool relu) {
#pragma unroll
    for (int mt = 0; mt < 2; mt++) {
        int rb = row0 + wm + mt * 16 + (lane >> 2);
#pragma unroll
        for (int nt = 0; nt < 8; nt++) {
            int cb = col0 + wn + nt * 8 + (lane & 3) * 2;
            float2 v0 = make_float2(c[mt][nt][0], c[mt][nt][1]);
            float2 v1 = make_float2(c[mt][nt][2], c[mt][nt][3]);
            if (relu) {
                v0.x = fmaxf(v0.x, 0.f); v0.y = fmaxf(v0.y, 0.f);
                v1.x = fmaxf(v1.x, 0.f); v1.y = fmaxf(v1.y, 0.f);
            }
            if (rb < M)     *(float2*)&C[(size_t)rb * NOUT + cb] = v0;
            if (rb + 8 < M) *(float2*)&C[(size_t)(rb + 8) * NOUT + cb] = v1;
        }
    }
}
__device__ __forceinline__ void bn_stats_epi(float c[2][8][4], float* statS, float* statQ,
                                             int col0, int wn, int lane) {
    float s16[16], q16[16];
#pragma unroll
    for (int nt = 0; nt < 8; nt++)
#pragma unroll
        for (int j = 0; j < 2; j++) {
            float a0 = c[0][nt][j], a1 = c[0][nt][j + 2];
            float a2 = c[1][nt][j], a3 = c[1][nt][j + 2];
            s16[nt * 2 + j] = a0 + a1 + a2 + a3;
            q16[nt * 2 + j] = a0 * a0 + a1 * a1 + a2 * a2 + a3 * a3;
        }
#pragma unroll
    for (int i = 0; i < 16; i++) {
#pragma unroll
        for (int off = 4; off < 32; off <<= 1) {
            s16[i] += __shfl_xor_sync(0xffffffffu, s16[i], off);
            q16[i] += __shfl_xor_sync(0xffffffffu, q16[i], off);
        }
    }
    if ((lane >> 2) == 0) {
#pragma unroll
        for (int nt = 0; nt < 8; nt++)
#pragma unroll
            for (int j = 0; j < 2; j++) {
                int col = col0 + wn + nt * 8 + (lane & 3) * 2 + j;
                atomicAdd(&statS[col], s16[nt * 2 + j]);
                atomicAdd(&statQ[col], q16[nt * 2 + j]);
            }
    }
}

// ===== GEMM1 3-pass (layer 0): A hi/lo fp16 x B hi/lo, fused BN stats =====
__global__ void __launch_bounds__(256, 2)
gemm1_p3(const __half* __restrict__ Ah, const __half* __restrict__ Al,
         const __half* __restrict__ Bh, const __half* __restrict__ Bl,
         float* __restrict__ C, float* __restrict__ statS, float* __restrict__ statQ,
         int M) {
    extern __shared__ __align__(128) char dsm[];
    const uint32_t base = smem_u32(dsm);
    constexpr int KTOT = 128, NOUT = 256, NC = 8;

    int tid = threadIdx.x;
    int wid = tid >> 5, lane = tid & 31;
    int wm = (wid & 3) * 32, wn = (wid >> 2) * 64;
    int row0 = blockIdx.y * 128, col0 = blockIdx.x * 128;
    int g = lane >> 3, r = lane & 7;

    float c[2][8][4];
#pragma unroll
    for (int i = 0; i < 2; i++)
#pragma unroll
        for (int j = 0; j < 8; j++)
#pragma unroll
            for (int q = 0; q < 4; q++) c[i][j][q] = 0.0f;

    auto stage = [&](int ch) {
        uint32_t b = base + (ch & 3) * CHSZ4;
        int k0 = ch * 16;
        seg_cp(b + 0 * SEG, Ah, row0, KTOT, k0, tid);
        seg_cp(b + 1 * SEG, Al, row0, KTOT, k0, tid);
        seg_cp(b + 2 * SEG, Bh, col0, KTOT, k0, tid);
        seg_cp(b + 3 * SEG, Bl, col0, KTOT, k0, tid);
        CP_COMMIT();
    };

    stage(0); stage(1); stage(2);

#pragma unroll 1
    for (int ch = 0; ch < NC - 3; ch++) {
        CP_WAIT2();
        __syncthreads();
        stage(ch + 3);
        mma_chunk3(base + (ch & 3) * CHSZ4, wm, wn, g, r, c);
    }
    CP_WAIT2(); __syncthreads();
    mma_chunk3(base + ((NC - 3) & 3) * CHSZ4, wm, wn, g, r, c);
    CP_WAIT1(); __syncthreads();
    mma_chunk3(base + ((NC - 2) & 3) * CHSZ4, wm, wn, g, r, c);
    CP_WAIT0(); __syncthreads();
    mma_chunk3(base + ((NC - 1) & 3) * CHSZ4, wm, wn, g, r, c);

    store_c(c, C, row0, col0, NOUT, wm, wn, lane, M, false);
    bn_stats_epi(c, statS, statQ, col0, wn, lane);
}

// ===== GEMM1 2-pass (layers 1,2,3): single-fp16 A x B hi/lo, z-batchable =====
__global__ void __launch_bounds__(256, 2)
gemm1_p2(const __half* __restrict__ A0, const __half* __restrict__ A1,
         const __half* __restrict__ Bh_base, const __half* __restrict__ Bl_base,
         float* __restrict__ C0, float* __restrict__ C1,
         float* __restrict__ statS_base, float* __restrict__ statQ_base, int M) {
    extern __shared__ __align__(128) char dsm[];
    const uint32_t base = smem_u32(dsm);
    constexpr int KTOT = 128, NOUT = 256, NC = 8;

    int z = blockIdx.z;
    const __half* Af = (z && !g_dualsame) ? A1 : A0;   // dedup when t2==t3
    const __half* Bh = Bh_base + (size_t)z * KTOT * NOUT;
    const __half* Bl = Bl_base + (size_t)z * KTOT * NOUT;
    float* C = z ? C1 : C0;

    int tid = threadIdx.x;
    int wid = tid >> 5, lane = tid & 31;
    int wm = (wid & 3) * 32, wn = (wid >> 2) * 64;
    int row0 = blockIdx.y * 128, col0 = blockIdx.x * 128;
    int g = lane >> 3, r = lane & 7;

    float c[2][8][4];
#pragma unroll
    for (int i = 0; i < 2; i++)
#pragma unroll
        for (int j = 0; j < 8; j++)
#pragma unroll
            for (int q = 0; q < 4; q++) c[i][j][q] = 0.0f;

    auto stage = [&](int ch) {
        uint32_t b = base + (ch & 3) * CHSZ3;
        int k0 = ch * 16;
        seg_cp(b + 0 * SEG, Af, row0, KTOT, k0, tid);
        seg_cp(b + 1 * SEG, Bh, col0, KTOT, k0, tid);
        seg_cp(b + 2 * SEG, Bl, col0, KTOT, k0, tid);
        CP_COMMIT();
    };

    stage(0); stage(1); stage(2);

#pragma unroll 1
    for (int ch = 0; ch < NC - 3; ch++) {
        CP_WAIT2();
        __syncthreads();
        stage(ch + 3);
        mma_chunk2(base + (ch & 3) * CHSZ3, wm, wn, g, r, c);
    }
    CP_WAIT2(); __syncthreads();
    mma_chunk2(base + ((NC - 3) & 3) * CHSZ3, wm, wn, g, r, c);
    CP_WAIT1(); __syncthreads();
    mma_chunk2(base + ((NC - 2) & 3) * CHSZ3, wm, wn, g, r, c);
    CP_WAIT0(); __syncthreads();
    mma_chunk2(base + ((NC - 1) & 3) * CHSZ3, wm, wn, g, r, c);

    store_c(c, C, row0, col0, NOUT, wm, wn, lane, M, false);
    bn_stats_epi(c, statS_base + z * DD2, statQ_base + z * DD2, col0, wn, lane);
}

// ===== GEMM2 3-pass (layer 0): fp32 A + fused-BN prolog -> fp16 hi/lo =====
__global__ void __launch_bounds__(256, 2)
gemm2_p3(const float* __restrict__ Af,
         const __half* __restrict__ Bh, const __half* __restrict__ Bl,
         float* __restrict__ C,
         const float* __restrict__ gamma, const float* __restrict__ beta,
         int l, int M) {
    extern __shared__ __align__(128) char dsm[];
    __shared__ float s_scale[DD2];
    __shared__ float s_shift[DD2];
    const uint32_t base = smem_u32(dsm);
    constexpr int KTOT = 256, NOUT = 128, NC = 16;

    int tid = threadIdx.x;
    int wid = tid >> 5, lane = tid & 31;
    int wm = (wid & 3) * 32, wn = (wid >> 2) * 64;
    int row0 = blockIdx.y * 128;
    int g = lane >> 3, r = lane & 7;

    {
        int cc = tid;
        float s = g_statS[l * DD2 + cc];
        float q = g_statQ[l * DD2 + cc];
        float mean = s / (float)M;
        float var = q / (float)M - mean * mean;
        float inv = rsqrtf(var + 1e-5f);
        float sc = inv * gamma[l * DD2 + cc];
        s_scale[cc] = sc;
        s_shift[cc] = beta[l * DD2 + cc] - mean * sc;
    }
    __syncthreads();

    float c[2][8][4];
#pragma unroll
    for (int i = 0; i < 2; i++)
#pragma unroll
        for (int j = 0; j < 8; j++)
#pragma unroll
            for (int q = 0; q < 4; q++) c[i][j][q] = 0.0f;

    int am = tid >> 1;
    int asub = tid & 1;
    float av[8];

    auto stageB = [&](int ch) {
        uint32_t b = base + (ch & 1) * CHSZ4;
        int k0 = ch * 16;
        seg_cp(b + 2 * SEG, Bh, 0, KTOT, k0, tid);
        seg_cp(b + 3 * SEG, Bl, 0, KTOT, k0, tid);
        CP_COMMIT();
    };
    auto ldgA = [&](int ch) {
        int row = row0 + am;
        int k0 = ch * 16 + asub * 8;
        if (row < M) {
            float4 u0 = *(const float4*)&Af[(size_t)row * KTOT + k0];
            float4 u1 = *(const float4*)&Af[(size_t)row * KTOT + k0 + 4];
            av[0]=u0.x; av[1]=u0.y; av[2]=u0.z; av[3]=u0.w;
            av[4]=u1.x; av[5]=u1.y; av[6]=u1.z; av[7]=u1.w;
        } else {
#pragma unroll
            for (int p = 0; p < 8; p++) av[p] = 0.f;
        }
    };
    auto stsA = [&](int ch) {
        uint32_t b = base + (ch & 1) * CHSZ4;
        int k0 = ch * 16 + asub * 8;
        uint32_t hp[4], lp[4];
#pragma unroll
        for (int p = 0; p < 4; p++) {
            float a0 = fmaxf(av[2*p]   * s_scale[k0 + 2*p]   + s_shift[k0 + 2*p],   0.f);
            float a1 = fmaxf(av[2*p+1] * s_scale[k0 + 2*p+1] + s_shift[k0 + 2*p+1], 0.f);
            __half2 hh = __floats2half2_rn(a0, a1);
            __half2 ll = __floats2half2_rn(a0 - __half2float(__low2half(hh)),
                                           a1 - __half2float(__high2half(hh)));
            hp[p] = *(uint32_t*)&hh;
            lp[p] = *(uint32_t*)&ll;
        }
        uint32_t off = (b - base) + am * STRD + asub * 16;
        *(uint4*)(dsm + off)       = make_uint4(hp[0], hp[1], hp[2], hp[3]);
        *(uint4*)(dsm + SEG + off) = make_uint4(lp[0], lp[1], lp[2], lp[3]);
    };

    stageB(0);
    ldgA(0);
    stsA(0);
    ldgA(1);
    CP_WAIT0();
    __syncthreads();

#pragma unroll 1
    for (int ch = 0; ch < NC; ch++) {
        bool hn = (ch + 1 < NC);
        if (hn) { stageB(ch + 1); stsA(ch + 1); }
        if (ch + 2 < NC) ldgA(ch + 2);
        mma_chunk3(base + (ch & 1) * CHSZ4, wm, wn, g, r, c);
        if (hn) CP_WAIT0();
        __syncthreads();
    }

    store_c(c, C, row0, 0, NOUT, wm, wn, lane, M, true);
}

// ===== GEMM2 2-pass (layer 1 and final mu/logstd): single-fp16 A prolog =====
template <bool RELU>
__global__ void __launch_bounds__(256, 2)
gemm2_p2(const float* __restrict__ A0, const float* __restrict__ A1,
         const __half* __restrict__ Bh_base, const __half* __restrict__ Bl_base,
         float* __restrict__ C0, float* __restrict__ C1,
         const float* __restrict__ gamma, const float* __restrict__ beta,
         int layer0, int M) {
    extern __shared__ __align__(128) char dsm[];
    __shared__ float s_scale[DD2];
    __shared__ float s_shift[DD2];
    const uint32_t base = smem_u32(dsm);
    constexpr int KTOT = 256, NOUT = 128, NC = 16;

    int z = blockIdx.z;
    int l = layer0 + z;
    const float* Af = z ? A1 : A0;
    const __half* Bh = Bh_base + (size_t)z * KTOT * NOUT;
    const __half* Bl = Bl_base + (size_t)z * KTOT * NOUT;
    float* C = z ? C1 : C0;

    int tid = threadIdx.x;
    int wid = tid >> 5, lane = tid & 31;
    int wm = (wid & 3) * 32, wn = (wid >> 2) * 64;
    int row0 = blockIdx.y * 128;
    int g = lane >> 3, r = lane & 7;

    {
        int cc = tid;
        float s = g_statS[l * DD2 + cc];
        float q = g_statQ[l * DD2 + cc];
        float mean = s / (float)M;
        float var = q / (float)M - mean * mean;
        float inv = rsqrtf(var + 1e-5f);
        float sc = inv * gamma[l * DD2 + cc];
        s_scale[cc] = sc;
        s_shift[cc] = beta[l * DD2 + cc] - mean * sc;
    }
    __syncthreads();

    float c[2][8][4];
#pragma unroll
    for (int i = 0; i < 2; i++)
#pragma unroll
        for (int j = 0; j < 8; j++)
#pragma unroll
            for (int q = 0; q < 4; q++) c[i][j][q] = 0.0f;

    int am = tid >> 1;
    int asub = tid & 1;
    float av[8];

    auto stageB = [&](int ch) {
        uint32_t b = base + (ch & 1) * CHSZ3;
        int k0 = ch * 16;
        seg_cp(b + 1 * SEG, Bh, 0, KTOT, k0, tid);
        seg_cp(b + 2 * SEG, Bl, 0, KTOT, k0, tid);
        CP_COMMIT();
    };
    auto ldgA = [&](int ch) {
        int row = row0 + am;
        int k0 = ch * 16 + asub * 8;
        if (row < M) {
            float4 u0 = *(const float4*)&Af[(size_t)row * KTOT + k0];
            float4 u1 = *(const float4*)&Af[(size_t)row * KTOT + k0 + 4];
            av[0]=u0.x; av[1]=u0.y; av[2]=u0.z; av[3]=u0.w;
            av[4]=u1.x; av[5]=u1.y; av[6]=u1.z; av[7]=u1.w;
        } else {
#pragma unroll
            for (int p = 0; p < 8; p++) av[p] = 0.f;
        }
    };
    auto stsA = [&](int ch) {
        uint32_t b = base + (ch & 1) * CHSZ3;
        int k0 = ch * 16 + asub * 8;
        uint32_t hp[4];
#pragma unroll
        for (int p = 0; p < 4; p++) {
            float a0 = fmaxf(av[2*p]   * s_scale[k0 + 2*p]   + s_shift[k0 + 2*p],   0.f);
            float a1 = fmaxf(av[2*p+1] * s_scale[k0 + 2*p+1] + s_shift[k0 + 2*p+1], 0.f);
            __half2 hh = __floats2half2_rn(a0, a1);
            hp[p] = *(uint32_t*)&hh;
        }
        uint32_t off = (b - base) + am * STRD + asub * 16;
        *(uint4*)(dsm + off) = make_uint4(hp[0], hp[1], hp[2], hp[3]);
    };

    stageB(0);
    ldgA(0);
    stsA(0);
    ldgA(1);
    CP_WAIT0();
    __syncthreads();

#pragma unroll 1
    for (int ch = 0; ch < NC; ch++) {
        bool hn = (ch + 1 < NC);
        if (hn) { stageB(ch + 1); stsA(ch + 1); }
        if (ch + 2 < NC) ldgA(ch + 2);
        mma_chunk2(base + (ch & 1) * CHSZ3, wm, wn, g, r, c);
        if (hn) CP_WAIT0();
        __syncthreads();
    }

    store_c(c, C, row0, 0, NOUT, wm, wn, lane, M, RELU);
}

// ===== weight pack (W1, W2 fp16 hi/lo) + zero stats/deg =====
__global__ void pack_w_kernel(const float* __restrict__ W1, const float* __restrict__ W2,
                              int N) {
    int idx = blockIdx.x * blockDim.x + threadIdx.x;
    if (idx < 131072) {
        int l = idx >> 15, rr = idx & 32767;
        int k = rr >> 8, n = rr & 255;
        float v = W1[(size_t)l * 32768 + rr];
        __half h = __float2half_rn(v);
        __half lo = __float2half_rn(v - __half2float(h));
        int o = l * 32768 + n * 128 + k;
        g_w1h[o] = h; g_w1l[o] = lo;
    } else if (idx < 262144) {
        int j = idx - 131072;
        int l = j >> 15, rr = j & 32767;
        int k = rr >> 7, n = rr & 127;
        float v = W2[(size_t)l * 32768 + rr];
        __half h = __float2half_rn(v);
        __half lo = __float2half_rn(v - __half2float(h));
        int o = l * 32768 + n * 256 + k;
        g_w2h[o] = h; g_w2l[o] = lo;
    }
    if (idx < 1024) { g_statS[idx] = 0.f; g_statQ[idx] = 0.f; }
    if (idx < N) g_deg[idx] = 0;
}

// ================= CSR build =================
__global__ void hist_kernel(const int* __restrict__ dst, int E, int N) {
    int e = blockIdx.x * blockDim.x + threadIdx.x;
    if (e >= E) return;
    int d = dst[e];
    if ((unsigned)d < (unsigned)N) atomicAdd(&g_deg[d], 1);
}
__global__ void blockscan_kernel(int N) {
    __shared__ int sm[256];
    int i = blockIdx.x * 256 + threadIdx.x;
    int v = (i < N) ? g_deg[i] : 0;
    sm[threadIdx.x] = v;
    __syncthreads();
#pragma unroll
    for (int off = 1; off < 256; off <<= 1) {
        int t = (threadIdx.x >= off) ? sm[threadIdx.x - off] : 0;
        __syncthreads();
        sm[threadIdx.x] += t;
        __syncthreads();
    }
    if (i < N) g_scan[i] = sm[threadIdx.x];
    if (threadIdx.x == 255) g_bsum[blockIdx.x] = sm[255];
}
__global__ void scanbsum_kernel(int nb) {
    __shared__ int sm[512];
    int tid = threadIdx.x;
    int v = (tid < nb) ? g_bsum[tid] : 0;
    sm[tid] = v;
    __syncthreads();
#pragma unroll
    for (int off = 1; off < 512; off <<= 1) {
        int t = (tid >= off) ? sm[tid - off] : 0;
        __syncthreads();
        sm[tid] += t;
        __syncthreads();
    }
    if (tid < nb) g_boff[tid] = sm[tid] - v;
}
__global__ void rowptr_kernel(int N, int E) {
    int i = blockIdx.x * 256 + threadIdx.x;
    if (i < N) {
        int rp = g_scan[i] - g_deg[i] + g_boff[blockIdx.x];
        g_rowptr[i] = rp;
        g_cursor[i] = rp;
    }
    if (i == 0) g_rowptr[N] = E;
}
__global__ void scatter_kernel(const int* __restrict__ src,
                               const int* __restrict__ dst, int E, int N) {
    int e = blockIdx.x * blockDim.x + threadIdx.x;
    if (e >= E) return;
    int d = dst[e];
    int s = src[e];
    if ((unsigned)d >= (unsigned)N || (unsigned)s >= (unsigned)N) return;
    int pos = atomicAdd(&g_cursor[d], 1);
    g_csr_src[pos] = s;
}

// ======== aggregation: no-max softmax (logits = relu(x)*t, bounded << 88) ====
__device__ __forceinline__ void supd(float v, float t, float& den, float& acc) {
    float msg = fmaxf(v, 0.0f) + 1e-7f;
    float w = __expf(msg * t);
    den += w;
    acc += w * msg;
}
__device__ __forceinline__ void pack_hl(const float* o, __half* H, __half* L,
                                        int gw, int lane) {
    __half2 h0 = __floats2half2_rn(o[0], o[1]);
    __half2 h1 = __floats2half2_rn(o[2], o[3]);
    __half2 l0 = __floats2half2_rn(o[0] - __low2float(h0), o[1] - __high2float(h0));
    __half2 l1 = __floats2half2_rn(o[2] - __low2float(h1), o[3] - __high2float(h1));
    uint2 uh, ul;
    uh.x = *(uint32_t*)&h0; uh.y = *(uint32_t*)&h1;
    ul.x = *(uint32_t*)&l0; ul.y = *(uint32_t*)&l1;
    ((uint2*)H)[gw * 32 + lane] = uh;
    ((uint2*)L)[gw * 32 + lane] = ul;
}
__device__ __forceinline__ void pack_f16(const float* o, __half* H, int gw, int lane) {
    __half2 p0 = __floats2half2_rn(o[0], o[1]);
    __half2 p1 = __floats2half2_rn(o[2], o[3]);
    uint2 u;
    u.x = *(uint32_t*)&p0;
    u.y = *(uint32_t*)&p1;
    ((uint2*)H)[gw * 32 + lane] = u;
}

// HILO: pack hi/lo (layer 0).  else: single fp16 (layer 1)
template <bool HILO>
__global__ void aggr_kernel(const float* __restrict__ x,
                            const float* __restrict__ t_all, int layer, int N) {
    int gw = (blockIdx.x * 256 + threadIdx.x) >> 5;
    int lane = threadIdx.x & 31;
    if (gw >= N) return;
    int beg = g_rowptr[gw], end = g_rowptr[gw + 1];
    float t = __ldg(&t_all[layer]);
    const float4* x4 = (const float4*)x;
    float d[4] = {0, 0, 0, 0}, a[4] = {0, 0, 0, 0};
    int sj = (beg < end) ? g_csr_src[beg] : 0;
    for (int j = beg; j < end; j++) {
        int s = sj;
        if (j + 1 < end) sj = g_csr_src[j + 1];
        float4 v = __ldg(&x4[s * 32 + lane]);
        supd(v.x, t, d[0], a[0]);
        supd(v.y, t, d[1], a[1]);
        supd(v.z, t, d[2], a[2]);
        supd(v.w, t, d[3], a[3]);
    }
    float4 xv = __ldg(&x4[gw * 32 + lane]);
    float xc[4] = {xv.x, xv.y, xv.z, xv.w};
    float o[4];
#pragma unroll
    for (int ci = 0; ci < 4; ci++) o[ci] = a[ci] / (d[ci] + 1e-16f) + xc[ci];
    if (HILO) pack_hl(o, g_ahh, g_ahl, gw, lane);
    else      pack_f16(o, g_af16, gw, lane);
}

__global__ void aggr_dual_kernel(const float* __restrict__ x,
                                 const float* __restrict__ t_all, int N) {
    int gw = (blockIdx.x * 256 + threadIdx.x) >> 5;
    int lane = threadIdx.x & 31;
    if (gw >= N) return;
    int beg = g_rowptr[gw], end = g_rowptr[gw + 1];
    float tA = __ldg(&t_all[2]);
    float tB = __ldg(&t_all[3]);
    const float4* x4 = (const float4*)x;
    float4 xv = __ldg(&x4[gw * 32 + lane]);
    float xc[4] = {xv.x, xv.y, xv.z, xv.w};

    if (tA == tB) {
        if (gw == 0 && lane == 0) g_dualsame = 1;
        float d[4] = {0, 0, 0, 0}, a[4] = {0, 0, 0, 0};
        int sj = (beg < end) ? g_csr_src[beg] : 0;
        for (int j = beg; j < end; j++) {
            int s = sj;
            if (j + 1 < end) sj = g_csr_src[j + 1];
            float4 v = __ldg(&x4[s * 32 + lane]);
            supd(v.x, tA, d[0], a[0]);
            supd(v.y, tA, d[1], a[1]);
            supd(v.z, tA, d[2], a[2]);
            supd(v.w, tA, d[3], a[3]);
        }
        float o[4];
#pragma unroll
        for (int ci = 0; ci < 4; ci++) o[ci] = a[ci] / (d[ci] + 1e-16f) + xc[ci];
        pack_f16(o, g_af16, gw, lane);   // single copy; consumers dedup via flag
    } else {
        if (gw == 0 && lane == 0) g_dualsame = 0;
        float dA[4] = {0, 0, 0, 0}, aA[4] = {0, 0, 0, 0};
        float dB[4] = {0, 0, 0, 0}, aB[4] = {0, 0, 0, 0};
        int sj = (beg < end) ? g_csr_src[beg] : 0;
        for (int j = beg; j < end; j++) {
            int s = sj;
            if (j + 1 < end) sj = g_csr_src[j + 1];
            float4 v = __ldg(&x4[s * 32 + lane]);
            float vv[4] = {v.x, v.y, v.z, v.w};
#pragma unroll
            for (int ci = 0; ci < 4; ci++) {
                supd(vv[ci], tA, dA[ci], aA[ci]);
                supd(vv[ci], tB, dB[ci], aB[ci]);
            }
        }
        float oA[4], oB[4];
#pragma unroll
        for (int ci = 0; ci < 4; ci++) {
            oA[ci] = aA[ci] / (dA[ci] + 1e-16f) + xc[ci];
            oB[ci] = aB[ci] / (dB[ci] + 1e-16f) + xc[ci];
        }
        pack_f16(oA, g_af16, gw, lane);
        pack_f16(oB, g_af16b, gw, lane);
    }
}

// ================= host orchestration =================
extern "C" void kernel_launch(void* const* d_in, const int* in_sizes, int n_in,
                              void* d_out, int out_size) {
    const float* x = (const float*)d_in[0];
    const int*   ei = (const int*)d_in[1];
    const float* t_all = (const float*)d_in[2];
    const float* W1 = (const float*)d_in[3];
    const float* W2 = (const float*)d_in[4];
    const float* gamma = (const float*)d_in[5];
    const float* beta = (const float*)d_in[6];

    const int N = in_sizes[0] / DD;
    const int E = in_sizes[1] / 2;
    const int* src = ei;
    const int* dst = ei + E;
    float* out = (float*)d_out;

    cudaFuncSetAttribute(gemm1_p3, cudaFuncAttributeMaxDynamicSharedMemorySize, 4 * CHSZ4);
    cudaFuncSetAttribute(gemm1_p2, cudaFuncAttributeMaxDynamicSharedMemorySize, 4 * CHSZ3);
    cudaFuncSetAttribute(gemm2_p3, cudaFuncAttributeMaxDynamicSharedMemorySize, 2 * CHSZ4);
    cudaFuncSetAttribute(gemm2_p2<true>, cudaFuncAttributeMaxDynamicSharedMemorySize, 2 * CHSZ3);
    cudaFuncSetAttribute(gemm2_p2<false>, cudaFuncAttributeMaxDynamicSharedMemorySize, 2 * CHSZ3);

    float* hA; cudaGetSymbolAddress((void**)&hA, g_hA);
    float* hB; cudaGetSymbolAddress((void**)&hB, g_hB);
    float* h1; cudaGetSymbolAddress((void**)&h1, g_h1);
    float* h1b; cudaGetSymbolAddress((void**)&h1b, g_h1b);
    float* sS; cudaGetSymbolAddress((void**)&sS, g_statS);
    float* sQ; cudaGetSymbolAddress((void**)&sQ, g_statQ);
    __half *ahh, *ahl, *af, *afb, *w1h, *w1l, *w2h, *w2l;
    cudaGetSymbolAddress((void**)&ahh, g_ahh);
    cudaGetSymbolAddress((void**)&ahl, g_ahl);
    cudaGetSymbolAddress((void**)&af, g_af16);
    cudaGetSymbolAddress((void**)&afb, g_af16b);
    cudaGetSymbolAddress((void**)&w1h, g_w1h);
    cudaGetSymbolAddress((void**)&w1l, g_w1l);
    cudaGetSymbolAddress((void**)&w2h, g_w2h);
    cudaGetSymbolAddress((void**)&w2l, g_w2l);

    const int mtiles = (N + 127) / 128;

    pack_w_kernel<<<1024, 256>>>(W1, W2, N);
    hist_kernel<<<(E + 255) / 256, 256>>>(dst, E, N);
    blockscan_kernel<<<NB, 256>>>(N);
    scanbsum_kernel<<<1, 512>>>(NB);
    rowptr_kernel<<<NB, 256>>>(N, E);
    scatter_kernel<<<(E + 255) / 256, 256>>>(src, dst, E, N);

    const int AG = (N * 32 + 255) / 256;

    // ---- layer 0 (3-pass everywhere; error crosses 3 layers) ----
    aggr_kernel<true><<<AG, 256>>>(x, t_all, 0, N);
    gemm1_p3<<<dim3(2, mtiles), 256, 4 * CHSZ4>>>(
        ahh, ahl, w1h + 0 * 32768, w1l + 0 * 32768, h1, sS + 0 * DD2, sQ + 0 * DD2, N);
    gemm2_p3<<<dim3(1, mtiles), 256, 2 * CHSZ4>>>(
        h1, w2h + 0 * 32768, w2l + 0 * 32768, hA, gamma, beta, 0, N);
    // ---- layer 1 (2-pass fp16; ~4e-4 injection, calibrated) ----
    aggr_kernel<false><<<AG, 256>>>(hA, t_all, 1, N);
    gemm1_p2<<<dim3(2, mtiles, 1), 256, 4 * CHSZ3>>>(
        af, af, w1h + 1 * 32768, w1l + 1 * 32768, h1, h1,
        sS + 1 * DD2, sQ + 1 * DD2, N);
    gemm2_p2<true><<<dim3(1, mtiles, 1), 256, 2 * CHSZ3>>>(
        h1, h1, w2h + 1 * 32768, w2l + 1 * 32768, hB, hB, gamma, beta, 1, N);
    // ---- layers 2 & 3 (mu, logstd): 2-pass, z-batched ----
    aggr_dual_kernel<<<AG, 256>>>(hB, t_all, N);
    gemm1_p2<<<dim3(2, mtiles, 2), 256, 4 * CHSZ3>>>(
        af, afb, w1h + 2 * 32768, w1l + 2 * 32768, h1, h1b,
        sS + 2 * DD2, sQ + 2 * DD2, N);
    gemm2_p2<false><<<dim3(1, mtiles, 2), 256, 2 * CHSZ3>>>(
        h1, h1b, w2h + 2 * 32768, w2l + 2 * 32768, out, out + (size_t)N * DD,
        gamma, beta, 2, N);
}

// round 17
// speedup vs baseline: 1.2503x; 1.0063x over previous
#include <cuda_runtime.h>
#include <cuda_fp16.h>
#include <math.h>
#include <stdint.h>

#define NN 100000
#define NPAD 100128
#define DD 128
#define DD2 256
#define EE 800000
#define NB ((NN + 255) / 256)
#define STRD 48          // k16 chunk: 16 elems*2B = 32B + 16B pad -> LDSM conflict-free
#define SEG 6144         // 128*48
#define CHSZ3 18432      // 3 segments (A, B_hi, B_lo)
#define CHSZ4 24576      // 4 segments (A_hi, A_lo, B_hi, B_lo)

// ================= scratch =================
__device__ float g_hA[NN * DD];
__device__ float g_hB[NN * DD];
__device__ float g_h1[NN * DD2];
__device__ float g_h1b[NN * DD2];
__device__ float g_statS[4 * DD2];
__device__ float g_statQ[4 * DD2];
__device__ int   g_dualsame;                           // t_all[2]==t_all[3] flag
__device__ __align__(256) __half g_ahh[NPAD * DD];   // aggr out hi (layer 0)
__device__ __align__(256) __half g_ahl[NPAD * DD];   // aggr out lo
__device__ __align__(256) __half g_af16[NPAD * DD];  // aggr out single fp16 (layers 1,2)
__device__ __align__(256) __half g_af16b[NPAD * DD]; // (layer 3; unused if dualsame)
__device__ __align__(256) __half g_w1h[4 * 256 * 128];  // [l][n][k] fp16 hi
__device__ __align__(256) __half g_w1l[4 * 256 * 128];
__device__ __align__(256) __half g_w2h[4 * 128 * 256];  // [l][n][k] fp16 hi
__device__ __align__(256) __half g_w2l[4 * 128 * 256];
__device__ int g_deg[NN];
__device__ int g_scan[NN];
__device__ int g_bsum[512];
__device__ int g_boff[512];
__device__ int g_rowptr[NN + 1];
__device__ int g_cursor[NN];
__device__ int g_csr_src[EE];

// ================= small helpers =================
__device__ __forceinline__ uint32_t smem_u32(const void* p) {
    uint32_t a;
    asm("{ .reg .u64 t; cvta.to.shared.u64 t, %1; cvt.u32.u64 %0, t; }"
        : "=r"(a) : "l"(p));
    return a;
}
#define CP_ASYNC16(sa, ga) \
    asm volatile("cp.async.cg.shared.global [%0], [%1], 16;" :: "r"(sa), "l"(ga))
#define CP_COMMIT() asm volatile("cp.async.commit_group;")
#define CP_WAIT0() asm volatile("cp.async.wait_group 0;")
#define CP_WAIT1() asm volatile("cp.async.wait_group 1;")
#define CP_WAIT2() asm volatile("cp.async.wait_group 2;")

__device__ __forceinline__ void ldsm_x4(uint32_t* r, uint32_t addr) {
    asm volatile("ldmatrix.sync.aligned.m8n8.x4.shared.b16 {%0,%1,%2,%3}, [%4];"
                 : "=r"(r[0]), "=r"(r[1]), "=r"(r[2]), "=r"(r[3]) : "r"(addr));
}
__device__ __forceinline__ void mma_f16(float* c, const uint32_t* a, const uint32_t* b) {
    asm volatile(
        "mma.sync.aligned.m16n8k16.row.col.f32.f16.f16.f32 "
        "{%0,%1,%2,%3}, {%4,%5,%6,%7}, {%8,%9}, {%0,%1,%2,%3};"
        : "+f"(c[0]), "+f"(c[1]), "+f"(c[2]), "+f"(c[3])
        : "r"(a[0]), "r"(a[1]), "r"(a[2]), "r"(a[3]), "r"(b[0]), "r"(b[1]));
}

// ---- 2-pass chunk: segs [A, Bh, Bl]; C += A*Bh + A*Bl. 10 LDSM + 32 MMA ----
__device__ __forceinline__ void mma_chunk2(uint32_t buf, int wm, int wn, int g, int r,
                                           float c[2][8][4]) {
    uint32_t a[2][4], bf[16];
    uint32_t acol = (uint32_t)(g >> 1) * 16;
    uint32_t bcol = (uint32_t)(g & 1) * 16;
#pragma unroll
    for (int mt = 0; mt < 2; mt++) {
        uint32_t arow = (uint32_t)(wm + mt * 16 + (g & 1) * 8 + r);
        ldsm_x4(a[mt], buf + arow * STRD + acol);
    }
#pragma unroll
    for (int nb = 0; nb < 4; nb++) {
        uint32_t brow = (uint32_t)(wn + nb * 16 + (g >> 1) * 8 + r);
        ldsm_x4(&bf[nb * 4], buf + SEG + brow * STRD + bcol);
    }
#pragma unroll
    for (int mt = 0; mt < 2; mt++)
#pragma unroll
        for (int nt = 0; nt < 8; nt++) mma_f16(c[mt][nt], a[mt], &bf[nt * 2]);
#pragma unroll
    for (int nb = 0; nb < 4; nb++) {
        uint32_t brow = (uint32_t)(wn + nb * 16 + (g >> 1) * 8 + r);
        ldsm_x4(&bf[nb * 4], buf + 2 * SEG + brow * STRD + bcol);
    }
#pragma unroll
    for (int mt = 0; mt < 2; mt++)
#pragma unroll
        for (int nt = 0; nt < 8; nt++) mma_f16(c[mt][nt], a[mt], &bf[nt * 2]);
}

// ---- 3-pass chunk: segs [Ah, Al, Bh, Bl]; C += Ah*Bh + Al*Bh + Ah*Bl ----
__device__ __forceinline__ void mma_chunk3(uint32_t buf, int wm, int wn, int g, int r,
                                           float c[2][8][4]) {
    uint32_t ah[2][4], al[2][4], bf[16];
    uint32_t acol = (uint32_t)(g >> 1) * 16;
    uint32_t bcol = (uint32_t)(g & 1) * 16;
#pragma unroll
    for (int mt = 0; mt < 2; mt++) {
        uint32_t arow = (uint32_t)(wm + mt * 16 + (g & 1) * 8 + r);
        ldsm_x4(ah[mt], buf + arow * STRD + acol);
        ldsm_x4(al[mt], buf + SEG + arow * STRD + acol);
    }
#pragma unroll
    for (int nb = 0; nb < 4; nb++) {
        uint32_t brow = (uint32_t)(wn + nb * 16 + (g >> 1) * 8 + r);
        ldsm_x4(&bf[nb * 4], buf + 2 * SEG + brow * STRD + bcol);
    }
#pragma unroll
    for (int mt = 0; mt < 2; mt++)
#pragma unroll
        for (int nt = 0; nt < 8; nt++) mma_f16(c[mt][nt], ah[mt], &bf[nt * 2]);
#pragma unroll
    for (int mt = 0; mt < 2; mt++)
#pragma unroll
        for (int nt = 0; nt < 8; nt++) mma_f16(c[mt][nt], al[mt], &bf[nt * 2]);
#pragma unroll
    for (int nb = 0; nb < 4; nb++) {
        uint32_t brow = (uint32_t)(wn + nb * 16 + (g >> 1) * 8 + r);
        ldsm_x4(&bf[nb * 4], buf + 3 * SEG + brow * STRD + bcol);
    }
#pragma unroll
    for (int mt = 0; mt < 2; mt++)
#pragma unroll
        for (int nt = 0; nt < 8; nt++) mma_f16(c[mt][nt], ah[mt], &bf[nt * 2]);
}

// cp.async one segment: 128 rows x 32B/row
template <typename T>
__device__ __forceinline__ void seg_cp(uint32_t sm, const T* gsrc,
                                       int row0g, int ldk, int k0, int tid) {
    int m = tid >> 1, sub = tid & 1;
    uint32_t sa = sm + m * STRD + sub * 16;
    const void* ga = gsrc + (size_t)(row0g + m) * ldk + k0 + sub * 8;
    CP_ASYNC16(sa, ga);
}

// ---- shared epilogue pieces ----
__device__ __forceinline__ void store_c(float c[2][8][4], float* C, int row0, int col0,
                                        int NOUT, int wm, int wn, int lane, int M,
                                        bool relu) {
#pragma unroll
    for (int mt = 0; mt < 2; mt++) {
        int rb = row0 + wm + mt * 16 + (lane >> 2);
#pragma unroll
        for (int nt = 0; nt < 8; nt++) {
            int cb = col0 + wn + nt * 8 + (lane & 3) * 2;
            float2 v0 = make_float2(c[mt][nt][0], c[mt][nt][1]);
            float2 v1 = make_float2(c[mt][nt][2], c[mt][nt][3]);
            if (relu) {
                v0.x = fmaxf(v0.x, 0.f); v0.y = fmaxf(v0.y, 0.f);
                v1.x = fmaxf(v1.x, 0.f); v1.y = fmaxf(v1.y, 0.f);
            }
            if (rb < M)     *(float2*)&C[(size_t)rb * NOUT + cb] = v0;
            if (rb + 8 < M) *(float2*)&C[(size_t)(rb + 8) * NOUT + cb] = v1;
        }
    }
}
__device__ __forceinline__ void bn_stats_epi(float c[2][8][4], float* statS, float* statQ,
                                             int col0, int wn, int lane) {
    float s16[16], q16[16];
#pragma unroll
    for (int nt = 0; nt < 8; nt++)
#pragma unroll
        for (int j = 0; j < 2; j++) {
            float a0 = c[0][nt][j], a1 = c[0][nt][j + 2];
            float a2 = c[1][nt][j], a3 = c[1][nt][j + 2];
            s16[nt * 2 + j] = a0 + a1 + a2 + a3;
            q16[nt * 2 + j] = a0 * a0 + a1 * a1 + a2 * a2 + a3 * a3;
        }
#pragma unroll
    for (int i = 0; i < 16; i++) {
#pragma unroll
        for (int off = 4; off < 32; off <<= 1) {
            s16[i] += __shfl_xor_sync(0xffffffffu, s16[i], off);
            q16[i] += __shfl_xor_sync(0xffffffffu, q16[i], off);
        }
    }
    if ((lane >> 2) == 0) {
#pragma unroll
        for (int nt = 0; nt < 8; nt++)
#pragma unroll
            for (int j = 0; j < 2; j++) {
                int col = col0 + wn + nt * 8 + (lane & 3) * 2 + j;
                atomicAdd(&statS[col], s16[nt * 2 + j]);
                atomicAdd(&statQ[col], q16[nt * 2 + j]);
            }
    }
}

// ===== GEMM1 3-pass (layer 0): A hi/lo fp16 x B hi/lo, fused BN stats =====
__global__ void __launch_bounds__(256, 2)
gemm1_p3(const __half* __restrict__ Ah, const __half* __restrict__ Al,
         const __half* __restrict__ Bh, const __half* __restrict__ Bl,
         float* __restrict__ C, float* __restrict__ statS, float* __restrict__ statQ,
         int M) {
    extern __shared__ __align__(128) char dsm[];
    const uint32_t base = smem_u32(dsm);
    constexpr int KTOT = 128, NOUT = 256, NC = 8;

    int tid = threadIdx.x;
    int wid = tid >> 5, lane = tid & 31;
    int wm = (wid & 3) * 32, wn = (wid >> 2) * 64;
    int row0 = blockIdx.y * 128, col0 = blockIdx.x * 128;
    int g = lane >> 3, r = lane & 7;

    float c[2][8][4];
#pragma unroll
    for (int i = 0; i < 2; i++)
#pragma unroll
        for (int j = 0; j < 8; j++)
#pragma unroll
            for (int q = 0; q < 4; q++) c[i][j][q] = 0.0f;

    auto stage = [&](int ch) {
        uint32_t b = base + (ch & 3) * CHSZ4;
        int k0 = ch * 16;
        seg_cp(b + 0 * SEG, Ah, row0, KTOT, k0, tid);
        seg_cp(b + 1 * SEG, Al, row0, KTOT, k0, tid);
        seg_cp(b + 2 * SEG, Bh, col0, KTOT, k0, tid);
        seg_cp(b + 3 * SEG, Bl, col0, KTOT, k0, tid);
        CP_COMMIT();
    };

    stage(0); stage(1); stage(2);

#pragma unroll 1
    for (int ch = 0; ch < NC - 3; ch++) {
        CP_WAIT2();
        __syncthreads();
        stage(ch + 3);
        mma_chunk3(base + (ch & 3) * CHSZ4, wm, wn, g, r, c);
    }
    CP_WAIT2(); __syncthreads();
    mma_chunk3(base + ((NC - 3) & 3) * CHSZ4, wm, wn, g, r, c);
    CP_WAIT1(); __syncthreads();
    mma_chunk3(base + ((NC - 2) & 3) * CHSZ4, wm, wn, g, r, c);
    CP_WAIT0(); __syncthreads();
    mma_chunk3(base + ((NC - 1) & 3) * CHSZ4, wm, wn, g, r, c);

    store_c(c, C, row0, col0, NOUT, wm, wn, lane, M, false);
    bn_stats_epi(c, statS, statQ, col0, wn, lane);
}

// ===== GEMM1 2-pass (layers 1,2,3): single-fp16 A x B hi/lo, z-batchable =====
__global__ void __launch_bounds__(256, 2)
gemm1_p2(const __half* __restrict__ A0, const __half* __restrict__ A1,
         const __half* __restrict__ Bh_base, const __half* __restrict__ Bl_base,
         float* __restrict__ C0, float* __restrict__ C1,
         float* __restrict__ statS_base, float* __restrict__ statQ_base, int M) {
    extern __shared__ __align__(128) char dsm[];
    const uint32_t base = smem_u32(dsm);
    constexpr int KTOT = 128, NOUT = 256, NC = 8;

    int z = blockIdx.z;
    int ds = __ldg(&g_dualsame);
    const __half* Af = (z && !ds) ? A1 : A0;   // dedup when t2==t3
    const __half* Bh = Bh_base + (size_t)z * KTOT * NOUT;
    const __half* Bl = Bl_base + (size_t)z * KTOT * NOUT;
    float* C = z ? C1 : C0;

    int tid = threadIdx.x;
    int wid = tid >> 5, lane = tid & 31;
    int wm = (wid & 3) * 32, wn = (wid >> 2) * 64;
    int row0 = blockIdx.y * 128, col0 = blockIdx.x * 128;
    int g = lane >> 3, r = lane & 7;

    float c[2][8][4];
#pragma unroll
    for (int i = 0; i < 2; i++)
#pragma unroll
        for (int j = 0; j < 8; j++)
#pragma unroll
            for (int q = 0; q < 4; q++) c[i][j][q] = 0.0f;

    auto stage = [&](int ch) {
        uint32_t b = base + (ch & 3) * CHSZ3;
        int k0 = ch * 16;
        seg_cp(b + 0 * SEG, Af, row0, KTOT, k0, tid);
        seg_cp(b + 1 * SEG, Bh, col0, KTOT, k0, tid);
        seg_cp(b + 2 * SEG, Bl, col0, KTOT, k0, tid);
        CP_COMMIT();
    };

    stage(0); stage(1); stage(2);

#pragma unroll 1
    for (int ch = 0; ch < NC - 3; ch++) {
        CP_WAIT2();
        __syncthreads();
        stage(ch + 3);
        mma_chunk2(base + (ch & 3) * CHSZ3, wm, wn, g, r, c);
    }
    CP_WAIT2(); __syncthreads();
    mma_chunk2(base + ((NC - 3) & 3) * CHSZ3, wm, wn, g, r, c);
    CP_WAIT1(); __syncthreads();
    mma_chunk2(base + ((NC - 2) & 3) * CHSZ3, wm, wn, g, r, c);
    CP_WAIT0(); __syncthreads();
    mma_chunk2(base + ((NC - 1) & 3) * CHSZ3, wm, wn, g, r, c);

    store_c(c, C, row0, col0, NOUT, wm, wn, lane, M, false);
    bn_stats_epi(c, statS_base + z * DD2, statQ_base + z * DD2, col0, wn, lane);
}

// ===== GEMM2 3-pass (layer 0): fp32 A + fused-BN prolog -> fp16 hi/lo =====
__global__ void __launch_bounds__(256, 2)
gemm2_p3(const float* __restrict__ Af,
         const __half* __restrict__ Bh, const __half* __restrict__ Bl,
         float* __restrict__ C,
         const float* __restrict__ gamma, const float* __restrict__ beta,
         int l, int M) {
    extern __shared__ __align__(128) char dsm[];
    __shared__ float s_scale[DD2];
    __shared__ float s_shift[DD2];
    const uint32_t base = smem_u32(dsm);
    constexpr int KTOT = 256, NOUT = 128, NC = 16;

    int tid = threadIdx.x;
    int wid = tid >> 5, lane = tid & 31;
    int wm = (wid & 3) * 32, wn = (wid >> 2) * 64;
    int row0 = blockIdx.y * 128;
    int g = lane >> 3, r = lane & 7;

    {
        int cc = tid;
        float s = g_statS[l * DD2 + cc];
        float q = g_statQ[l * DD2 + cc];
        float mean = s / (float)M;
        float var = q / (float)M - mean * mean;
        float inv = rsqrtf(var + 1e-5f);
        float sc = inv * gamma[l * DD2 + cc];
        s_scale[cc] = sc;
        s_shift[cc] = beta[l * DD2 + cc] - mean * sc;
    }
    __syncthreads();

    float c[2][8][4];
#pragma unroll
    for (int i = 0; i < 2; i++)
#pragma unroll
        for (int j = 0; j < 8; j++)
#pragma unroll
            for (int q = 0; q < 4; q++) c[i][j][q] = 0.0f;

    int am = tid >> 1;
    int asub = tid & 1;
    float av[8];

    auto stageB = [&](int ch) {
        uint32_t b = base + (ch & 1) * CHSZ4;
        int k0 = ch * 16;
        seg_cp(b + 2 * SEG, Bh, 0, KTOT, k0, tid);
        seg_cp(b + 3 * SEG, Bl, 0, KTOT, k0, tid);
        CP_COMMIT();
    };
    auto ldgA = [&](int ch) {
        int row = row0 + am;
        int k0 = ch * 16 + asub * 8;
        if (row < M) {
            float4 u0 = *(const float4*)&Af[(size_t)row * KTOT + k0];
            float4 u1 = *(const float4*)&Af[(size_t)row * KTOT + k0 + 4];
            av[0]=u0.x; av[1]=u0.y; av[2]=u0.z; av[3]=u0.w;
            av[4]=u1.x; av[5]=u1.y; av[6]=u1.z; av[7]=u1.w;
        } else {
#pragma unroll
            for (int p = 0; p < 8; p++) av[p] = 0.f;
        }
    };
    auto stsA = [&](int ch) {
        uint32_t b = base + (ch & 1) * CHSZ4;
        int k0 = ch * 16 + asub * 8;
        uint32_t hp[4], lp[4];
#pragma unroll
        for (int p = 0; p < 4; p++) {
            float a0 = fmaxf(av[2*p]   * s_scale[k0 + 2*p]   + s_shift[k0 + 2*p],   0.f);
            float a1 = fmaxf(av[2*p+1] * s_scale[k0 + 2*p+1] + s_shift[k0 + 2*p+1], 0.f);
            __half2 hh = __floats2half2_rn(a0, a1);
            __half2 ll = __floats2half2_rn(a0 - __half2float(__low2half(hh)),
                                           a1 - __half2float(__high2half(hh)));
            hp[p] = *(uint32_t*)&hh;
            lp[p] = *(uint32_t*)&ll;
        }
        uint32_t off = (b - base) + am * STRD + asub * 16;
        *(uint4*)(dsm + off)       = make_uint4(hp[0], hp[1], hp[2], hp[3]);
        *(uint4*)(dsm + SEG + off) = make_uint4(lp[0], lp[1], lp[2], lp[3]);
    };

    stageB(0);
    ldgA(0);
    stsA(0);
    ldgA(1);
    CP_WAIT0();
    __syncthreads();

#pragma unroll 1
    for (int ch = 0; ch < NC; ch++) {
        bool hn = (ch + 1 < NC);
        if (hn) { stageB(ch + 1); stsA(ch + 1); }
        if (ch + 2 < NC) ldgA(ch + 2);
        mma_chunk3(base + (ch & 1) * CHSZ4, wm, wn, g, r, c);
        if (hn) CP_WAIT0();
        __syncthreads();
    }

    store_c(c, C, row0, 0, NOUT, wm, wn, lane, M, true);
}

// ===== GEMM2 2-pass (layer 1 and final mu/logstd): single-fp16 A prolog =====
template <bool RELU>
__global__ void __launch_bounds__(256, 2)
gemm2_p2(const float* __restrict__ A0, const float* __restrict__ A1,
         const __half* __restrict__ Bh_base, const __half* __restrict__ Bl_base,
         float* __restrict__ C0, float* __restrict__ C1,
         const float* __restrict__ gamma, const float* __restrict__ beta,
         int layer0, int M) {
    extern __shared__ __align__(128) char dsm[];
    __shared__ float s_scale[DD2];
    __shared__ float s_shift[DD2];
    const uint32_t base = smem_u32(dsm);
    constexpr int KTOT = 256, NOUT = 128, NC = 16;

    int z = blockIdx.z;
    int l = layer0 + z;
    const float* Af = z ? A1 : A0;
    const __half* Bh = Bh_base + (size_t)z * KTOT * NOUT;
    const __half* Bl = Bl_base + (size_t)z * KTOT * NOUT;
    float* C = z ? C1 : C0;

    int tid = threadIdx.x;
    int wid = tid >> 5, lane = tid & 31;
    int wm = (wid & 3) * 32, wn = (wid >> 2) * 64;
    int row0 = blockIdx.y * 128;
    int g = lane >> 3, r = lane & 7;

    {
        int cc = tid;
        float s = g_statS[l * DD2 + cc];
        float q = g_statQ[l * DD2 + cc];
        float mean = s / (float)M;
        float var = q / (float)M - mean * mean;
        float inv = rsqrtf(var + 1e-5f);
        float sc = inv * gamma[l * DD2 + cc];
        s_scale[cc] = sc;
        s_shift[cc] = beta[l * DD2 + cc] - mean * sc;
    }
    __syncthreads();

    float c[2][8][4];
#pragma unroll
    for (int i = 0; i < 2; i++)
#pragma unroll
        for (int j = 0; j < 8; j++)
#pragma unroll
            for (int q = 0; q < 4; q++) c[i][j][q] = 0.0f;

    int am = tid >> 1;
    int asub = tid & 1;
    float av[8];

    auto stageB = [&](int ch) {
        uint32_t b = base + (ch & 1) * CHSZ3;
        int k0 = ch * 16;
        seg_cp(b + 1 * SEG, Bh, 0, KTOT, k0, tid);
        seg_cp(b + 2 * SEG, Bl, 0, KTOT, k0, tid);
        CP_COMMIT();
    };
    auto ldgA = [&](int ch) {
        int row = row0 + am;
        int k0 = ch * 16 + asub * 8;
        if (row < M) {
            float4 u0 = *(const float4*)&Af[(size_t)row * KTOT + k0];
            float4 u1 = *(const float4*)&Af[(size_t)row * KTOT + k0 + 4];
            av[0]=u0.x; av[1]=u0.y; av[2]=u0.z; av[3]=u0.w;
            av[4]=u1.x; av[5]=u1.y; av[6]=u1.z; av[7]=u1.w;
        } else {
#pragma unroll
            for (int p = 0; p < 8; p++) av[p] = 0.f;
        }
    };
    auto stsA = [&](int ch) {
        uint32_t b = base + (ch & 1) * CHSZ3;
        int k0 = ch * 16 + asub * 8;
        uint32_t hp[4];
#pragma unroll
        for (int p = 0; p < 4; p++) {
            float a0 = fmaxf(av[2*p]   * s_scale[k0 + 2*p]   + s_shift[k0 + 2*p],   0.f);
            float a1 = fmaxf(av[2*p+1] * s_scale[k0 + 2*p+1] + s_shift[k0 + 2*p+1], 0.f);
            __half2 hh = __floats2half2_rn(a0, a1);
            hp[p] = *(uint32_t*)&hh;
        }
        uint32_t off = (b - base) + am * STRD + asub * 16;
        *(uint4*)(dsm + off) = make_uint4(hp[0], hp[1], hp[2], hp[3]);
    };

    stageB(0);
    ldgA(0);
    stsA(0);
    ldgA(1);
    CP_WAIT0();
    __syncthreads();

#pragma unroll 1
    for (int ch = 0; ch < NC; ch++) {
        bool hn = (ch + 1 < NC);
        if (hn) { stageB(ch + 1); stsA(ch + 1); }
        if (ch + 2 < NC) ldgA(ch + 2);
        mma_chunk2(base + (ch & 1) * CHSZ3, wm, wn, g, r, c);
        if (hn) CP_WAIT0();
        __syncthreads();
    }

    store_c(c, C, row0, 0, NOUT, wm, wn, lane, M, RELU);
}

// ===== weight pack (W1, W2 fp16 hi/lo) + zero stats/deg =====
__global__ void pack_w_kernel(const float* __restrict__ W1, const float* __restrict__ W2,
                              int N) {
    int idx = blockIdx.x * blockDim.x + threadIdx.x;
    if (idx < 131072) {
        int l = idx >> 15, rr = idx & 32767;
        int k = rr >> 8, n = rr & 255;
        float v = W1[(size_t)l * 32768 + rr];
        __half h = __float2half_rn(v);
        __half lo = __float2half_rn(v - __half2float(h));
        int o = l * 32768 + n * 128 + k;
        g_w1h[o] = h; g_w1l[o] = lo;
    } else if (idx < 262144) {
        int j = idx - 131072;
        int l = j >> 15, rr = j & 32767;
        int k = rr >> 7, n = rr & 127;
        float v = W2[(size_t)l * 32768 + rr];
        __half h = __float2half_rn(v);
        __half lo = __float2half_rn(v - __half2float(h));
        int o = l * 32768 + n * 256 + k;
        g_w2h[o] = h; g_w2l[o] = lo;
    }
    if (idx < 1024) { g_statS[idx] = 0.f; g_statQ[idx] = 0.f; }
    if (idx < N) g_deg[idx] = 0;
}

// ================= CSR build (indices in [0,N) by dataset construction) ======
__global__ void hist_kernel(const int* __restrict__ dst, int E) {
    int e = blockIdx.x * blockDim.x + threadIdx.x;
    if (e >= E) return;
    atomicAdd(&g_deg[dst[e]], 1);
}
__global__ void blockscan_kernel(int N) {
    __shared__ int sm[256];
    int i = blockIdx.x * 256 + threadIdx.x;
    int v = (i < N) ? g_deg[i] : 0;
    sm[threadIdx.x] = v;
    __syncthreads();
#pragma unroll
    for (int off = 1; off < 256; off <<= 1) {
        int t = (threadIdx.x >= off) ? sm[threadIdx.x - off] : 0;
        __syncthreads();
        sm[threadIdx.x] += t;
        __syncthreads();
    }
    if (i < N) g_scan[i] = sm[threadIdx.x];
    if (threadIdx.x == 255) g_bsum[blockIdx.x] = sm[255];
}
__global__ void scanbsum_kernel(int nb) {
    __shared__ int sm[512];
    int tid = threadIdx.x;
    int v = (tid < nb) ? g_bsum[tid] : 0;
    sm[tid] = v;
    __syncthreads();
#pragma unroll
    for (int off = 1; off < 512; off <<= 1) {
        int t = (tid >= off) ? sm[tid - off] : 0;
        __syncthreads();
        sm[tid] += t;
        __syncthreads();
    }
    if (tid < nb) g_boff[tid] = sm[tid] - v;
}
__global__ void rowptr_kernel(int N, int E) {
    int i = blockIdx.x * 256 + threadIdx.x;
    if (i < N) {
        int rp = g_scan[i] - g_deg[i] + g_boff[blockIdx.x];
        g_rowptr[i] = rp;
        g_cursor[i] = rp;
    }
    if (i == 0) g_rowptr[N] = E;
}
__global__ void scatter_kernel(const int* __restrict__ src,
                               const int* __restrict__ dst, int E) {
    int e = blockIdx.x * blockDim.x + threadIdx.x;
    if (e >= E) return;
    int pos = atomicAdd(&g_cursor[dst[e]], 1);
    g_csr_src[pos] = src[e];
}

// ======== aggregation: no-max softmax (logits = relu(x)*t, bounded << 88) ====
__device__ __forceinline__ void supd(float v, float t, float& den, float& acc) {
    float msg = fmaxf(v, 0.0f) + 1e-7f;
    float w = __expf(msg * t);
    den += w;
    acc += w * msg;
}
__device__ __forceinline__ void pack_hl(const float* o, __half* H, __half* L,
                                        int gw, int lane) {
    __half2 h0 = __floats2half2_rn(o[0], o[1]);
    __half2 h1 = __floats2half2_rn(o[2], o[3]);
    __half2 l0 = __floats2half2_rn(o[0] - __low2float(h0), o[1] - __high2float(h0));
    __half2 l1 = __floats2half2_rn(o[2] - __low2float(h1), o[3] - __high2float(h1));
    uint2 uh, ul;
    uh.x = *(uint32_t*)&h0; uh.y = *(uint32_t*)&h1;
    ul.x = *(uint32_t*)&l0; ul.y = *(uint32_t*)&l1;
    ((uint2*)H)[gw * 32 + lane] = uh;
    ((uint2*)L)[gw * 32 + lane] = ul;
}
__device__ __forceinline__ void pack_f16(const float* o, __half* H, int gw, int lane) {
    __half2 p0 = __floats2half2_rn(o[0], o[1]);
    __half2 p1 = __floats2half2_rn(o[2], o[3]);
    uint2 u;
    u.x = *(uint32_t*)&p0;
    u.y = *(uint32_t*)&p1;
    ((uint2*)H)[gw * 32 + lane] = u;
}

// HILO: pack hi/lo (layer 0).  else: single fp16 (layer 1)
template <bool HILO>
__global__ void aggr_kernel(const float* __restrict__ x,
                            const float* __restrict__ t_all, int layer, int N) {
    int gw = (blockIdx.x * 256 + threadIdx.x) >> 5;
    int lane = threadIdx.x & 31;
    if (gw >= N) return;
    int beg = g_rowptr[gw], end = g_rowptr[gw + 1];
    float t = __ldg(&t_all[layer]);
    const float4* x4 = (const float4*)x;
    float d[4] = {0, 0, 0, 0}, a[4] = {0, 0, 0, 0};
    int sj = (beg < end) ? g_csr_src[beg] : 0;
    for (int j = beg; j < end; j++) {
        int s = sj;
        if (j + 1 < end) sj = g_csr_src[j + 1];
        float4 v = __ldg(&x4[s * 32 + lane]);
        supd(v.x, t, d[0], a[0]);
        supd(v.y, t, d[1], a[1]);
        supd(v.z, t, d[2], a[2]);
        supd(v.w, t, d[3], a[3]);
    }
    float4 xv = __ldg(&x4[gw * 32 + lane]);
    float xc[4] = {xv.x, xv.y, xv.z, xv.w};
    float o[4];
#pragma unroll
    for (int ci = 0; ci < 4; ci++) o[ci] = a[ci] / (d[ci] + 1e-16f) + xc[ci];
    if (HILO) pack_hl(o, g_ahh, g_ahl, gw, lane);
    else      pack_f16(o, g_af16, gw, lane);
}

__global__ void aggr_dual_kernel(const float* __restrict__ x,
                                 const float* __restrict__ t_all, int N) {
    int gw = (blockIdx.x * 256 + threadIdx.x) >> 5;
    int lane = threadIdx.x & 31;
    if (gw >= N) return;
    int beg = g_rowptr[gw], end = g_rowptr[gw + 1];
    float tA = __ldg(&t_all[2]);
    float tB = __ldg(&t_all[3]);
    const float4* x4 = (const float4*)x;
    float4 xv = __ldg(&x4[gw * 32 + lane]);
    float xc[4] = {xv.x, xv.y, xv.z, xv.w};

    if (tA == tB) {
        if (gw == 0 && lane == 0) g_dualsame = 1;
        float d[4] = {0, 0, 0, 0}, a[4] = {0, 0, 0, 0};
        int sj = (beg < end) ? g_csr_src[beg] : 0;
        for (int j = beg; j < end; j++) {
            int s = sj;
            if (j + 1 < end) sj = g_csr_src[j + 1];
            float4 v = __ldg(&x4[s * 32 + lane]);
            supd(v.x, tA, d[0], a[0]);
            supd(v.y, tA, d[1], a[1]);
            supd(v.z, tA, d[2], a[2]);
            supd(v.w, tA, d[3], a[3]);
        }
        float o[4];
#pragma unroll
        for (int ci = 0; ci < 4; ci++) o[ci] = a[ci] / (d[ci] + 1e-16f) + xc[ci];
        pack_f16(o, g_af16, gw, lane);   // single copy; consumers dedup via flag
    } else {
        if (gw == 0 && lane == 0) g_dualsame = 0;
        float dA[4] = {0, 0, 0, 0}, aA[4] = {0, 0, 0, 0};
        float dB[4] = {0, 0, 0, 0}, aB[4] = {0, 0, 0, 0};
        int sj = (beg < end) ? g_csr_src[beg] : 0;
        for (int j = beg; j < end; j++) {
            int s = sj;
            if (j + 1 < end) sj = g_csr_src[j + 1];
            float4 v = __ldg(&x4[s * 32 + lane]);
            float vv[4] = {v.x, v.y, v.z, v.w};
#pragma unroll
            for (int ci = 0; ci < 4; ci++) {
                supd(vv[ci], tA, dA[ci], aA[ci]);
                supd(vv[ci], tB, dB[ci], aB[ci]);
            }
        }
        float oA[4], oB[4];
#pragma unroll
        for (int ci = 0; ci < 4; ci++) {
            oA[ci] = aA[ci] / (dA[ci] + 1e-16f) + xc[ci];
            oB[ci] = aB[ci] / (dB[ci] + 1e-16f) + xc[ci];
        }
        pack_f16(oA, g_af16, gw, lane);
        pack_f16(oB, g_af16b, gw, lane);
    }
}

// ================= host orchestration =================
extern "C" void kernel_launch(void* const* d_in, const int* in_sizes, int n_in,
                              void* d_out, int out_size) {
    const float* x = (const float*)d_in[0];
    const int*   ei = (const int*)d_in[1];
    const float* t_all = (const float*)d_in[2];
    const float* W1 = (const float*)d_in[3];
    const float* W2 = (const float*)d_in[4];
    const float* gamma = (const float*)d_in[5];
    const float* beta = (const float*)d_in[6];

    const int N = in_sizes[0] / DD;
    const int E = in_sizes[1] / 2;
    const int* src = ei;
    const int* dst = ei + E;
    float* out = (float*)d_out;

    cudaFuncSetAttribute(gemm1_p3, cudaFuncAttributeMaxDynamicSharedMemorySize, 4 * CHSZ4);
    cudaFuncSetAttribute(gemm1_p2, cudaFuncAttributeMaxDynamicSharedMemorySize, 4 * CHSZ3);
    cudaFuncSetAttribute(gemm2_p3, cudaFuncAttributeMaxDynamicSharedMemorySize, 2 * CHSZ4);
    cudaFuncSetAttribute(gemm2_p2<true>, cudaFuncAttributeMaxDynamicSharedMemorySize, 2 * CHSZ3);
    cudaFuncSetAttribute(gemm2_p2<false>, cudaFuncAttributeMaxDynamicSharedMemorySize, 2 * CHSZ3);

    float* hA; cudaGetSymbolAddress((void**)&hA, g_hA);
    float* hB; cudaGetSymbolAddress((void**)&hB, g_hB);
    float* h1; cudaGetSymbolAddress((void**)&h1, g_h1);
    float* h1b; cudaGetSymbolAddress((void**)&h1b, g_h1b);
    float* sS; cudaGetSymbolAddress((void**)&sS, g_statS);
    float* sQ; cudaGetSymbolAddress((void**)&sQ, g_statQ);
    __half *ahh, *ahl, *af, *afb, *w1h, *w1l, *w2h, *w2l;
    cudaGetSymbolAddress((void**)&ahh, g_ahh);
    cudaGetSymbolAddress((void**)&ahl, g_ahl);
    cudaGetSymbolAddress((void**)&af, g_af16);
    cudaGetSymbolAddress((void**)&afb, g_af16b);
    cudaGetSymbolAddress((void**)&w1h, g_w1h);
    cudaGetSymbolAddress((void**)&w1l, g_w1l);
    cudaGetSymbolAddress((void**)&w2h, g_w2h);
    cudaGetSymbolAddress((void**)&w2l, g_w2l);

    const int mtiles = (N + 127) / 128;

    pack_w_kernel<<<1024, 256>>>(W1, W2, N);
    hist_kernel<<<(E + 255) / 256, 256>>>(dst, E);
    blockscan_kernel<<<NB, 256>>>(N);
    scanbsum_kernel<<<1, 512>>>(NB);
    rowptr_kernel<<<NB, 256>>>(N, E);
    scatter_kernel<<<(E + 255) / 256, 256>>>(src, dst, E);

    const int AG = (N * 32 + 255) / 256;

    // ---- layer 0 (3-pass everywhere; error crosses 3 layers) ----
    aggr_kernel<true><<<AG, 256>>>(x, t_all, 0, N);
    gemm1_p3<<<dim3(2, mtiles), 256, 4 * CHSZ4>>>(
        ahh, ahl, w1h + 0 * 32768, w1l + 0 * 32768, h1, sS + 0 * DD2, sQ + 0 * DD2, N);
    gemm2_p3<<<dim3(1, mtiles), 256, 2 * CHSZ4>>>(
        h1, w2h + 0 * 32768, w2l + 0 * 32768, hA, gamma, beta, 0, N);
    // ---- layer 1 (2-pass fp16; calibrated error budget) ----
    aggr_kernel<false><<<AG, 256>>>(hA, t_all, 1, N);
    gemm1_p2<<<dim3(2, mtiles, 1), 256, 4 * CHSZ3>>>(
        af, af, w1h + 1 * 32768, w1l + 1 * 32768, h1, h1,
        sS + 1 * DD2, sQ + 1 * DD2, N);
    gemm2_p2<true><<<dim3(1, mtiles, 1), 256, 2 * CHSZ3>>>(
        h1, h1, w2h + 1 * 32768, w2l + 1 * 32768, hB, hB, gamma, beta, 1, N);
    // ---- layers 2 & 3 (mu, logstd): 2-pass, z-batched ----
    aggr_dual_kernel<<<AG, 256>>>(hB, t_all, N);
    gemm1_p2<<<dim3(2, mtiles, 2), 256, 4 * CHSZ3>>>(
        af, afb, w1h + 2 * 32768, w1l + 2 * 32768, h1, h1b,
        sS + 2 * DD2, sQ + 2 * DD2, N);
    gemm2_p2<false><<<dim3(1, mtiles, 2), 256, 2 * CHSZ3>>>(
        h1, h1b, w2h + 2 * 32768, w2l + 2 * 32768, out, out + (size_t)N * DD,
        gamma, beta, 2, N);
}